// round 1
// baseline (speedup 1.0000x reference)
#include <cuda_runtime.h>
#include <math.h>

#define NN 50000
#define EE 400000
#define EPP 40000
#define FF 64
#define EDD 32
#define HH 128
#define LL 2

// ---------------- scratch (device globals; no allocation allowed) ----------------
__device__ float g_x[NN * HH];
__device__ float g_ea[EE * HH];
__device__ float g_eenc[EE * HH];
__device__ float g_upd[EE * HH];
__device__ float g_post[NN * HH];
__device__ float g_lin[NN * HH];
__device__ float g_s1[NN * HH];   // becomes mean after finalize
__device__ float g_s2[NN * HH];   // becomes std after finalize
__device__ float g_mn[NN * HH];
__device__ float g_mx[NN * HH];
__device__ int   g_deg[NN];
__device__ float g_amp[NN];
__device__ float g_att[NN];
__device__ float g_bnsum[HH];
__device__ float g_bnsq[HH];
__device__ float g_bnmu[HH];
__device__ float g_bnrstd[HH];

// ---------------- atomic float min/max ----------------
__device__ __forceinline__ void atomicMaxF(float* a, float v) {
    if (v >= 0.f) atomicMax((int*)a, __float_as_int(v));
    else          atomicMin((unsigned int*)a, __float_as_uint(v));
}
__device__ __forceinline__ void atomicMinF(float* a, float v) {
    if (v >= 0.f) atomicMin((int*)a, __float_as_int(v));
    else          atomicMax((unsigned int*)a, __float_as_uint(v));
}

// ---------------- A-tile loaders ----------------
struct PlainLd {
    const float* __restrict__ A; int K;
    __device__ __forceinline__ float operator()(int r, int k) const { return A[(long)r * K + k]; }
};
struct GatherLd {  // [x[i0[r]], x[i1[r]], third[r]]  (each 128 wide)
    const float* __restrict__ x;
    const int* __restrict__ i0;
    const int* __restrict__ i1;
    const float* __restrict__ third;
    __device__ __forceinline__ float operator()(int r, int k) const {
        if (k < 128) return x[(long)i0[r] * 128 + k];
        if (k < 256) return x[(long)i1[r] * 128 + (k - 128)];
        return third[(long)r * 128 + (k - 256)];
    }
};
struct PostLd {  // [x, agg, agg*amp, agg*att]; agg = [mean, mn, mx, std]
    const float* __restrict__ x;
    const float* __restrict__ mean;
    const float* __restrict__ mn;
    const float* __restrict__ mx;
    const float* __restrict__ sd;
    const float* __restrict__ amp;
    const float* __restrict__ att;
    __device__ __forceinline__ float operator()(int r, int k) const {
        if (k < 128) return x[(long)r * 128 + k];
        int jj  = k - 128;
        int grp = jj >> 9;        // 0: raw, 1: *amp, 2: *att
        int rem = jj & 511;
        int a   = rem >> 7;       // 0 mean, 1 mn, 2 mx, 3 std
        int c   = rem & 127;
        const float* base = (a == 0) ? mean : (a == 1) ? mn : (a == 2) ? mx : sd;
        float v = base[(long)r * 128 + c];
        if (grp == 1) v *= amp[r];
        else if (grp == 2) v *= att[r];
        return v;
    }
};

// ---------------- epilogues ----------------
struct StoreEp {
    float* __restrict__ o;
    __device__ __forceinline__ void operator()(int r, int c, float v) const { o[(long)r * 128 + c] = v; }
};
struct ReluEp {
    float* __restrict__ o;
    __device__ __forceinline__ void operator()(int r, int c, float v) const { o[(long)r * 128 + c] = fmaxf(v, 0.f); }
};
struct EaEp {  // ea += v/2
    float* __restrict__ ea;
    __device__ __forceinline__ void operator()(int r, int c, float v) const {
        long i = (long)r * 128 + c;
        ea[i] = ea[i] + 0.5f * v;
    }
};
struct AggEp {  // segment sum / sumsq / min / max over dst
    float* __restrict__ s1; float* __restrict__ s2;
    float* __restrict__ mn; float* __restrict__ mx;
    const int* __restrict__ dst;
    __device__ __forceinline__ void operator()(int r, int c, float v) const {
        long o = (long)dst[r] * 128 + c;
        atomicAdd(s1 + o, v);
        atomicAdd(s2 + o, v * v);
        atomicMaxF(mx + o, v);
        atomicMinF(mn + o, v);
    }
};

// ---------------- generic tiled GEMM: out[M,128] = A[M,K] @ W[K,128] + b ----------------
template <typename Loader, typename Epi>
__global__ void __launch_bounds__(256) gemm128_kernel(
    Loader ld, Epi ep,
    const float* __restrict__ W, const float* __restrict__ bias,
    int M, int K)
{
    __shared__ float As[32][33];
    __shared__ float Ws[32][128];
    const int tid = threadIdx.x;
    const int tx = tid & 31;   // col group: cols tx*4 .. tx*4+3
    const int ty = tid >> 5;   // row group: rows ty*4 .. ty*4+3
    const int row0 = blockIdx.x * 32;

    float acc[4][4] = {};

    for (int k0 = 0; k0 < K; k0 += 32) {
        // load A tile (32 rows x 32 k)
#pragma unroll
        for (int i = 0; i < 4; i++) {
            int e = tid + 256 * i;
            int r = e >> 5, kk = e & 31;
            int grow = row0 + r;
            As[r][kk] = (grow < M) ? ld(grow, k0 + kk) : 0.f;
        }
        // load W tile (32 k x 128 cols), vectorized
#pragma unroll
        for (int i = 0; i < 4; i++) {
            int e = tid + 256 * i;           // float4 index 0..1023
            int kk = e >> 5, c4 = e & 31;
            ((float4*)&Ws[kk][0])[c4] = ((const float4*)&W[(long)(k0 + kk) * 128])[c4];
        }
        __syncthreads();
#pragma unroll
        for (int kk = 0; kk < 32; kk++) {
            float a0 = As[ty * 4 + 0][kk];
            float a1 = As[ty * 4 + 1][kk];
            float a2 = As[ty * 4 + 2][kk];
            float a3 = As[ty * 4 + 3][kk];
            float4 b = *(const float4*)&Ws[kk][tx * 4];
            acc[0][0] += a0 * b.x; acc[0][1] += a0 * b.y; acc[0][2] += a0 * b.z; acc[0][3] += a0 * b.w;
            acc[1][0] += a1 * b.x; acc[1][1] += a1 * b.y; acc[1][2] += a1 * b.z; acc[1][3] += a1 * b.w;
            acc[2][0] += a2 * b.x; acc[2][1] += a2 * b.y; acc[2][2] += a2 * b.z; acc[2][3] += a2 * b.w;
            acc[3][0] += a3 * b.x; acc[3][1] += a3 * b.y; acc[3][2] += a3 * b.z; acc[3][3] += a3 * b.w;
        }
        __syncthreads();
    }

#pragma unroll
    for (int i = 0; i < 4; i++) {
        int grow = row0 + ty * 4 + i;
        if (grow < M) {
#pragma unroll
            for (int j = 0; j < 4; j++) {
                int c = tx * 4 + j;
                ep(grow, c, acc[i][j] + bias[c]);
            }
        }
    }
}

// ---------------- small kernels ----------------
__global__ void k_zero_deg() {
    int i = blockIdx.x * blockDim.x + threadIdx.x;
    if (i < NN) g_deg[i] = 0;
}
__global__ void k_count_deg(const int* __restrict__ dst) {
    int e = blockIdx.x * blockDim.x + threadIdx.x;
    if (e < EE) atomicAdd(&g_deg[dst[e]], 1);
}
__global__ void k_amp_att(const float* __restrict__ adl) {
    int i = blockIdx.x * blockDim.x + threadIdx.x;
    if (i < NN) {
        float d = fmaxf((float)g_deg[i], 1.f);
        float lg = logf(d + 1.f);
        float a = adl[0];
        g_amp[i] = lg / a;
        g_att[i] = a / lg;
    }
}
__global__ void k_init_agg() {
    long i = (long)blockIdx.x * blockDim.x + threadIdx.x;
    if (i < (long)NN * HH) {
        g_s1[i] = 0.f;
        g_s2[i] = 0.f;
        g_mn[i] = __int_as_float(0x7f800000);   // +inf
        g_mx[i] = __int_as_float(0xff800000);   // -inf
    }
}
__global__ void k_zero_bn() {
    int c = threadIdx.x;
    g_bnsum[c] = 0.f;
    g_bnsq[c] = 0.f;
}
__global__ void k_fin_agg() {
    long i = (long)blockIdx.x * blockDim.x + threadIdx.x;
    if (i < (long)NN * HH) {
        int n = (int)(i >> 7);
        int d = g_deg[n];
        float degc = fmaxf((float)d, 1.f);
        float m = g_s1[i] / degc;
        float var = g_s2[i] / degc - m * m;
        g_s1[i] = m;
        g_s2[i] = sqrtf(fmaxf(var, 0.f) + 1e-5f);
        if (d == 0) { g_mn[i] = 0.f; g_mx[i] = 0.f; }
    }
}
__global__ void k_bn_stats(const float* __restrict__ o) {
    int c = threadIdx.x;           // 128 threads
    float s = 0.f, s2 = 0.f;
    for (int r = blockIdx.x; r < NN; r += gridDim.x) {
        float v = o[(long)r * 128 + c];
        s += v; s2 += v * v;
    }
    atomicAdd(&g_bnsum[c], s);
    atomicAdd(&g_bnsq[c], s2);
}
__global__ void k_bn_fin() {
    int c = threadIdx.x;
    float mu = g_bnsum[c] / (float)NN;
    float var = g_bnsq[c] / (float)NN - mu * mu;
    g_bnmu[c] = mu;
    g_bnrstd[c] = rsqrtf(var + 1e-5f);
}
__global__ void k_apply(const float* __restrict__ bng, const float* __restrict__ bnb) {
    long i = (long)blockIdx.x * blockDim.x + threadIdx.x;
    if (i < (long)NN * HH) {
        int c = (int)(i & 127);
        float v = bng[c] * (g_lin[i] - g_bnmu[c]) * g_bnrstd[c] + bnb[c];
        g_x[i] = (g_x[i] + fmaxf(v, 0.f)) * 0.5f;
    }
}
__global__ void k_copy_x(float* __restrict__ o) {
    long i = (long)blockIdx.x * blockDim.x + threadIdx.x;
    if (i < (long)NN * HH) o[i] = g_x[i];
}

// ---------------- launch ----------------
extern "C" void kernel_launch(void* const* d_in, const int* in_sizes, int n_in,
                              void* d_out, int out_size) {
    const float* x_in       = (const float*)d_in[0];
    const int*   eidx       = (const int*)  d_in[1];
    const float* edge_attr  = (const float*)d_in[2];
    // d_in[3] pos_edge_index unused by reference
    const float* pos_attr   = (const float*)d_in[4];
    // d_in[5] neg_edge_index unused
    const float* neg_attr   = (const float*)d_in[6];
    const float* avg_dl     = (const float*)d_in[7];
    const float* node_emb_w = (const float*)d_in[8];
    const float* node_emb_b = (const float*)d_in[9];
    const float* edge_emb_w = (const float*)d_in[10];
    const float* edge_emb_b = (const float*)d_in[11];
    const float* eenc_w     = (const float*)d_in[12];
    const float* eenc_b     = (const float*)d_in[13];
    const float* pre_w      = (const float*)d_in[14];
    const float* pre_b      = (const float*)d_in[15];
    const float* post_w     = (const float*)d_in[16];
    const float* post_b     = (const float*)d_in[17];
    const float* lin_w      = (const float*)d_in[18];
    const float* lin_b      = (const float*)d_in[19];
    const float* emlp_w1    = (const float*)d_in[20];
    const float* emlp_b1    = (const float*)d_in[21];
    const float* emlp_w2    = (const float*)d_in[22];
    const float* emlp_b2    = (const float*)d_in[23];
    const float* bn_g       = (const float*)d_in[24];
    const float* bn_b       = (const float*)d_in[25];

    const int* src = eidx;          // edge_index[0]
    const int* dst = eidx + EE;     // edge_index[1]

    float* out     = (float*)d_out;
    float* pos_out = out + (long)NN * HH;
    float* neg_out = pos_out + (long)EPP * HH;

    // device pointers to scratch
    float *p_x, *p_ea, *p_eenc, *p_upd, *p_post, *p_lin, *p_s1, *p_s2, *p_mn, *p_mx, *p_amp, *p_att;
    cudaGetSymbolAddress((void**)&p_x, g_x);
    cudaGetSymbolAddress((void**)&p_ea, g_ea);
    cudaGetSymbolAddress((void**)&p_eenc, g_eenc);
    cudaGetSymbolAddress((void**)&p_upd, g_upd);
    cudaGetSymbolAddress((void**)&p_post, g_post);
    cudaGetSymbolAddress((void**)&p_lin, g_lin);
    cudaGetSymbolAddress((void**)&p_s1, g_s1);
    cudaGetSymbolAddress((void**)&p_s2, g_s2);
    cudaGetSymbolAddress((void**)&p_mn, g_mn);
    cudaGetSymbolAddress((void**)&p_mx, g_mx);
    cudaGetSymbolAddress((void**)&p_amp, g_amp);
    cudaGetSymbolAddress((void**)&p_att, g_att);

    const int NB_N  = (NN + 31) / 32;      // 1563
    const int NB_E  = (EE + 31) / 32;      // 12500
    const int NB_EP = (EPP + 31) / 32;     // 1250
    const int TPB = 256;
    const int GB_N = (NN + TPB - 1) / TPB;
    const int GB_E = (EE + TPB - 1) / TPB;
    const long NH = (long)NN * HH;
    const int GB_NH = (int)((NH + TPB - 1) / TPB);

    // degree + amp/att (static over layers)
    k_zero_deg<<<GB_N, TPB>>>();
    k_count_deg<<<GB_E, TPB>>>(dst);
    k_amp_att<<<GB_N, TPB>>>(avg_dl);

    // embeddings
    gemm128_kernel<<<NB_N, 256>>>(PlainLd{x_in, FF}, StoreEp{p_x}, node_emb_w, node_emb_b, NN, FF);
    gemm128_kernel<<<NB_E, 256>>>(PlainLd{edge_attr, EDD}, StoreEp{p_ea}, edge_emb_w, edge_emb_b, EE, EDD);
    gemm128_kernel<<<NB_EP, 256>>>(PlainLd{pos_attr, EDD}, StoreEp{pos_out}, edge_emb_w, edge_emb_b, EPP, EDD);
    gemm128_kernel<<<NB_EP, 256>>>(PlainLd{neg_attr, EDD}, StoreEp{neg_out}, edge_emb_w, edge_emb_b, EPP, EDD);

    for (int l = 0; l < LL; l++) {
        const float* eW  = eenc_w  + (long)l * HH * HH;
        const float* eB  = eenc_b  + (long)l * HH;
        const float* pW  = pre_w   + (long)l * 3 * HH * HH;
        const float* pB  = pre_b   + (long)l * HH;
        const float* poW = post_w  + (long)l * 13 * HH * HH;
        const float* poB = post_b  + (long)l * HH;
        const float* lW  = lin_w   + (long)l * HH * HH;
        const float* lB  = lin_b   + (long)l * HH;
        const float* m1W = emlp_w1 + (long)l * 3 * HH * HH;
        const float* m1B = emlp_b1 + (long)l * HH;
        const float* m2W = emlp_w2 + (long)l * HH * HH;
        const float* m2B = emlp_b2 + (long)l * HH;
        const float* bG  = bn_g    + (long)l * HH;
        const float* bB  = bn_b    + (long)l * HH;

        k_init_agg<<<GB_NH, TPB>>>();
        k_zero_bn<<<1, HH>>>();

        // e_enc = ea @ eenc_w + b
        gemm128_kernel<<<NB_E, 256>>>(PlainLd{p_ea, HH}, StoreEp{p_eenc}, eW, eB, EE, HH);

        // h = [x[dst], x[src], e_enc] @ pre_w + b   (fused segment agg epilogue)
        gemm128_kernel<<<NB_E, 256>>>(GatherLd{p_x, dst, src, p_eenc},
                                      AggEp{p_s1, p_s2, p_mn, p_mx, dst}, pW, pB, EE, 3 * HH);

        k_fin_agg<<<GB_NH, TPB>>>();

        // out = [x, agg, agg*amp, agg*att] @ post_w + b
        gemm128_kernel<<<NB_N, 256>>>(PostLd{p_x, p_s1, p_mn, p_mx, p_s2, p_amp, p_att},
                                      StoreEp{p_post}, poW, poB, NN, 13 * HH);
        // out = out @ lin_w + b
        gemm128_kernel<<<NB_N, 256>>>(PlainLd{p_post, HH}, StoreEp{p_lin}, lW, lB, NN, HH);

        k_bn_stats<<<256, HH>>>(p_lin);
        k_bn_fin<<<1, HH>>>();
        k_apply<<<GB_NH, TPB>>>(bG, bB);

        // upd = relu([x[src], x[dst], ea] @ emlp_w1 + b1)
        gemm128_kernel<<<NB_E, 256>>>(GatherLd{p_x, src, dst, p_ea},
                                      ReluEp{p_upd}, m1W, m1B, EE, 3 * HH);
        // ea = ea + (upd @ emlp_w2 + b2) / 2
        gemm128_kernel<<<NB_E, 256>>>(PlainLd{p_upd, HH}, EaEp{p_ea}, m2W, m2B, EE, HH);
    }

    k_copy_x<<<GB_NH, TPB>>>(out);
}

// round 2
// speedup vs baseline: 1.7039x; 1.7039x over previous
#include <cuda_runtime.h>
#include <math.h>

#define NN 50000
#define EE 400000
#define EPP 40000
#define FF 64
#define EDD 32
#define HH 128
#define LL 2

// ---------------- scratch (device globals; no allocation allowed) ----------------
__device__ float g_x[NN * HH];
__device__ float g_ea[EE * HH];
__device__ float g_eenc[EE * HH];
__device__ float g_upd[EE * HH];
__device__ float g_post[NN * HH];
__device__ float g_lin[NN * HH];
__device__ float g_s1[NN * HH];   // becomes mean after finalize
__device__ float g_s2[NN * HH];   // becomes std after finalize
__device__ float g_mn[NN * HH];
__device__ float g_mx[NN * HH];
__device__ int   g_deg[NN];
__device__ float g_amp[NN];
__device__ float g_att[NN];
__device__ float g_bnsum[HH];
__device__ float g_bnsq[HH];
__device__ float g_bnmu[HH];
__device__ float g_bnrstd[HH];

// ---------------- packed f32x2 helpers ----------------
typedef unsigned long long u64t;
__device__ __forceinline__ u64t pk2(float x, float y) {
    u64t r; asm("mov.b64 %0, {%1, %2};" : "=l"(r) : "f"(x), "f"(y)); return r;
}
__device__ __forceinline__ void upk2(u64t v, float& x, float& y) {
    asm("mov.b64 {%0, %1}, %2;" : "=f"(x), "=f"(y) : "l"(v));
}
__device__ __forceinline__ void fma2(u64t& c, u64t a, u64t b) {
    asm("fma.rn.f32x2 %0, %1, %2, %0;" : "+l"(c) : "l"(a), "l"(b));
}

// ---------------- atomic float min/max ----------------
__device__ __forceinline__ void atomicMaxF(float* a, float v) {
    if (v >= 0.f) atomicMax((int*)a, __float_as_int(v));
    else          atomicMin((unsigned int*)a, __float_as_uint(v));
}
__device__ __forceinline__ void atomicMinF(float* a, float v) {
    if (v >= 0.f) atomicMin((int*)a, __float_as_int(v));
    else          atomicMax((unsigned int*)a, __float_as_uint(v));
}

// ---------------- A-tile loaders (load4: 4 consecutive k, k%4==0, K%16==0) ----------------
struct PlainLd {
    const float* __restrict__ A; int K;
    __device__ __forceinline__ float4 load4(int r, int k) const {
        return *(const float4*)(A + (long)r * K + k);
    }
};
struct GatherLd {  // [x[i0[r]], x[i1[r]], third[r]]  (each 128 wide)
    const float* __restrict__ x;
    const int* __restrict__ i0;
    const int* __restrict__ i1;
    const float* __restrict__ third;
    __device__ __forceinline__ float4 load4(int r, int k) const {
        if (k < 128) return *(const float4*)(x + (long)i0[r] * 128 + k);
        if (k < 256) return *(const float4*)(x + (long)i1[r] * 128 + (k - 128));
        return *(const float4*)(third + (long)r * 128 + (k - 256));
    }
};
struct PostLd {  // [x, agg, agg*amp, agg*att]; agg = [mean, mn, mx, std]
    const float* __restrict__ x;
    const float* __restrict__ mean;
    const float* __restrict__ mn;
    const float* __restrict__ mx;
    const float* __restrict__ sd;
    const float* __restrict__ amp;
    const float* __restrict__ att;
    __device__ __forceinline__ float4 load4(int r, int k) const {
        if (k < 128) return *(const float4*)(x + (long)r * 128 + k);
        int jj  = k - 128;
        int grp = jj >> 9;        // 0: raw, 1: *amp, 2: *att
        int rem = jj & 511;
        int a   = rem >> 7;       // 0 mean, 1 mn, 2 mx, 3 std
        int c   = rem & 127;
        const float* base = (a == 0) ? mean : (a == 1) ? mn : (a == 2) ? mx : sd;
        float4 v = *(const float4*)(base + (long)r * 128 + c);
        float s = (grp == 1) ? amp[r] : (grp == 2) ? att[r] : 1.f;
        v.x *= s; v.y *= s; v.z *= s; v.w *= s;
        return v;
    }
};

// ---------------- epilogues ----------------
struct StoreEp {
    float* __restrict__ o;
    __device__ __forceinline__ void operator()(int r, int c, float v) const { o[(long)r * 128 + c] = v; }
};
struct ReluEp {
    float* __restrict__ o;
    __device__ __forceinline__ void operator()(int r, int c, float v) const { o[(long)r * 128 + c] = fmaxf(v, 0.f); }
};
struct EaEp {  // ea += v/2
    float* __restrict__ ea;
    __device__ __forceinline__ void operator()(int r, int c, float v) const {
        long i = (long)r * 128 + c;
        ea[i] = ea[i] + 0.5f * v;
    }
};
struct AggEp {  // segment sum / sumsq / min / max over dst
    float* __restrict__ s1; float* __restrict__ s2;
    float* __restrict__ mn; float* __restrict__ mx;
    const int* __restrict__ dst;
    __device__ __forceinline__ void operator()(int r, int c, float v) const {
        long o = (long)dst[r] * 128 + c;
        atomicAdd(s1 + o, v);
        atomicAdd(s2 + o, v * v);
        atomicMaxF(mx + o, v);
        atomicMinF(mn + o, v);
    }
};

// ---------------- tiled GEMM: out[M,128] = A[M,K] @ W[K,128] + b ----------------
// 128x128 block tile, 256 threads, 8x8 per thread, K-tile 16, FFMA2 inner loop.
#define APAD 17
template <typename Loader, typename Epi>
__global__ void __launch_bounds__(256, 2) gemm128_kernel(
    Loader ld, Epi ep,
    const float* __restrict__ W, const float* __restrict__ bias,
    int M, int K)
{
    __shared__ float As[128 * APAD];     // [row][k] padded
    __shared__ float Ws[16 * 128];       // [k][col]
    const int tid = threadIdx.x;
    const int tx = tid & 15;   // col group: cols tx*8 .. tx*8+7
    const int ty = tid >> 4;   // row group: rows ty*8 .. ty*8+7
    const int row0 = blockIdx.x * 128;

    u64t acc[4][8];   // [rowpair][col]  (.x = row 2p, .y = row 2p+1)
#pragma unroll
    for (int p = 0; p < 4; p++)
#pragma unroll
        for (int c = 0; c < 8; c++) acc[p][c] = 0ull;

    for (int k0 = 0; k0 < K; k0 += 16) {
        // load A tile: 128 rows x 16 k. Each thread: 2 float4 chunks.
#pragma unroll
        for (int i = 0; i < 2; i++) {
            int f = tid + 256 * i;           // 0..511
            int r = f >> 2, kq = f & 3;
            int grow = row0 + r;
            float4 v = make_float4(0.f, 0.f, 0.f, 0.f);
            if (grow < M) v = ld.load4(grow, k0 + kq * 4);
            float* dstp = &As[r * APAD + kq * 4];
            dstp[0] = v.x; dstp[1] = v.y; dstp[2] = v.z; dstp[3] = v.w;
        }
        // load W tile: 16 k x 128 cols. Each thread: 2 float4.
#pragma unroll
        for (int i = 0; i < 2; i++) {
            int f = tid + 256 * i;           // float4 index 0..511
            int kk = f >> 5, c4 = f & 31;
            *(float4*)&Ws[kk * 128 + c4 * 4] = *(const float4*)&W[(long)(k0 + kk) * 128 + c4 * 4];
        }
        __syncthreads();

        const float* arow = &As[(ty * 8) * APAD];
#pragma unroll
        for (int kk = 0; kk < 16; kk++) {
            float4 b0 = *(const float4*)&Ws[kk * 128 + tx * 8];
            float4 b1 = *(const float4*)&Ws[kk * 128 + tx * 8 + 4];
            u64t bb[8];
            bb[0] = pk2(b0.x, b0.x); bb[1] = pk2(b0.y, b0.y);
            bb[2] = pk2(b0.z, b0.z); bb[3] = pk2(b0.w, b0.w);
            bb[4] = pk2(b1.x, b1.x); bb[5] = pk2(b1.y, b1.y);
            bb[6] = pk2(b1.z, b1.z); bb[7] = pk2(b1.w, b1.w);
#pragma unroll
            for (int p = 0; p < 4; p++) {
                u64t a2 = pk2(arow[(2 * p) * APAD + kk], arow[(2 * p + 1) * APAD + kk]);
#pragma unroll
                for (int c = 0; c < 8; c++) fma2(acc[p][c], a2, bb[c]);
            }
        }
        __syncthreads();
    }

    // epilogue
    float bvals[8];
#pragma unroll
    for (int c = 0; c < 8; c++) bvals[c] = bias[tx * 8 + c];
#pragma unroll
    for (int p = 0; p < 4; p++) {
        int r0g = row0 + ty * 8 + 2 * p;
#pragma unroll
        for (int c = 0; c < 8; c++) {
            float v0, v1;
            upk2(acc[p][c], v0, v1);
            int col = tx * 8 + c;
            if (r0g < M)     ep(r0g,     col, v0 + bvals[c]);
            if (r0g + 1 < M) ep(r0g + 1, col, v1 + bvals[c]);
        }
    }
}

// ---------------- small kernels ----------------
__global__ void k_zero_deg() {
    int i = blockIdx.x * blockDim.x + threadIdx.x;
    if (i < NN) g_deg[i] = 0;
}
__global__ void k_count_deg(const int* __restrict__ dst) {
    int e = blockIdx.x * blockDim.x + threadIdx.x;
    if (e < EE) atomicAdd(&g_deg[dst[e]], 1);
}
__global__ void k_amp_att(const float* __restrict__ adl) {
    int i = blockIdx.x * blockDim.x + threadIdx.x;
    if (i < NN) {
        float d = fmaxf((float)g_deg[i], 1.f);
        float lg = logf(d + 1.f);
        float a = adl[0];
        g_amp[i] = lg / a;
        g_att[i] = a / lg;
    }
}
__global__ void k_init_agg() {
    long i = (long)blockIdx.x * blockDim.x + threadIdx.x;
    if (i < (long)NN * HH) {
        g_s1[i] = 0.f;
        g_s2[i] = 0.f;
        g_mn[i] = __int_as_float(0x7f800000);   // +inf
        g_mx[i] = __int_as_float(0xff800000);   // -inf
    }
}
__global__ void k_zero_bn() {
    int c = threadIdx.x;
    g_bnsum[c] = 0.f;
    g_bnsq[c] = 0.f;
}
__global__ void k_fin_agg() {
    long i = (long)blockIdx.x * blockDim.x + threadIdx.x;
    if (i < (long)NN * HH) {
        int n = (int)(i >> 7);
        int d = g_deg[n];
        float degc = fmaxf((float)d, 1.f);
        float m = g_s1[i] / degc;
        float var = g_s2[i] / degc - m * m;
        g_s1[i] = m;
        g_s2[i] = sqrtf(fmaxf(var, 0.f) + 1e-5f);
        if (d == 0) { g_mn[i] = 0.f; g_mx[i] = 0.f; }
    }
}
__global__ void k_bn_stats(const float* __restrict__ o) {
    int c = threadIdx.x;           // 128 threads
    float s = 0.f, s2 = 0.f;
    for (int r = blockIdx.x; r < NN; r += gridDim.x) {
        float v = o[(long)r * 128 + c];
        s += v; s2 += v * v;
    }
    atomicAdd(&g_bnsum[c], s);
    atomicAdd(&g_bnsq[c], s2);
}
__global__ void k_bn_fin() {
    int c = threadIdx.x;
    float mu = g_bnsum[c] / (float)NN;
    float var = g_bnsq[c] / (float)NN - mu * mu;
    g_bnmu[c] = mu;
    g_bnrstd[c] = rsqrtf(var + 1e-5f);
}
__global__ void k_apply(const float* __restrict__ bng, const float* __restrict__ bnb) {
    long i = (long)blockIdx.x * blockDim.x + threadIdx.x;
    if (i < (long)NN * HH) {
        int c = (int)(i & 127);
        float v = bng[c] * (g_lin[i] - g_bnmu[c]) * g_bnrstd[c] + bnb[c];
        g_x[i] = (g_x[i] + fmaxf(v, 0.f)) * 0.5f;
    }
}
__global__ void k_copy_x(float* __restrict__ o) {
    long i = (long)blockIdx.x * blockDim.x + threadIdx.x;
    if (i < (long)NN * HH) o[i] = g_x[i];
}

// ---------------- launch ----------------
extern "C" void kernel_launch(void* const* d_in, const int* in_sizes, int n_in,
                              void* d_out, int out_size) {
    const float* x_in       = (const float*)d_in[0];
    const int*   eidx       = (const int*)  d_in[1];
    const float* edge_attr  = (const float*)d_in[2];
    const float* pos_attr   = (const float*)d_in[4];
    const float* neg_attr   = (const float*)d_in[6];
    const float* avg_dl     = (const float*)d_in[7];
    const float* node_emb_w = (const float*)d_in[8];
    const float* node_emb_b = (const float*)d_in[9];
    const float* edge_emb_w = (const float*)d_in[10];
    const float* edge_emb_b = (const float*)d_in[11];
    const float* eenc_w     = (const float*)d_in[12];
    const float* eenc_b     = (const float*)d_in[13];
    const float* pre_w      = (const float*)d_in[14];
    const float* pre_b      = (const float*)d_in[15];
    const float* post_w     = (const float*)d_in[16];
    const float* post_b     = (const float*)d_in[17];
    const float* lin_w      = (const float*)d_in[18];
    const float* lin_b      = (const float*)d_in[19];
    const float* emlp_w1    = (const float*)d_in[20];
    const float* emlp_b1    = (const float*)d_in[21];
    const float* emlp_w2    = (const float*)d_in[22];
    const float* emlp_b2    = (const float*)d_in[23];
    const float* bn_g       = (const float*)d_in[24];
    const float* bn_b       = (const float*)d_in[25];

    const int* src = eidx;          // edge_index[0]
    const int* dst = eidx + EE;     // edge_index[1]

    float* out     = (float*)d_out;
    float* pos_out = out + (long)NN * HH;
    float* neg_out = pos_out + (long)EPP * HH;

    float *p_x, *p_ea, *p_eenc, *p_upd, *p_post, *p_lin, *p_s1, *p_s2, *p_mn, *p_mx, *p_amp, *p_att;
    cudaGetSymbolAddress((void**)&p_x, g_x);
    cudaGetSymbolAddress((void**)&p_ea, g_ea);
    cudaGetSymbolAddress((void**)&p_eenc, g_eenc);
    cudaGetSymbolAddress((void**)&p_upd, g_upd);
    cudaGetSymbolAddress((void**)&p_post, g_post);
    cudaGetSymbolAddress((void**)&p_lin, g_lin);
    cudaGetSymbolAddress((void**)&p_s1, g_s1);
    cudaGetSymbolAddress((void**)&p_s2, g_s2);
    cudaGetSymbolAddress((void**)&p_mn, g_mn);
    cudaGetSymbolAddress((void**)&p_mx, g_mx);
    cudaGetSymbolAddress((void**)&p_amp, g_amp);
    cudaGetSymbolAddress((void**)&p_att, g_att);

    const int NB_N  = (NN + 127) / 128;
    const int NB_E  = (EE + 127) / 128;      // 3125 exact
    const int NB_EP = (EPP + 127) / 128;
    const int TPB = 256;
    const int GB_N = (NN + TPB - 1) / TPB;
    const int GB_E = (EE + TPB - 1) / TPB;
    const long NH = (long)NN * HH;
    const int GB_NH = (int)((NH + TPB - 1) / TPB);

    // degree + amp/att (static over layers)
    k_zero_deg<<<GB_N, TPB>>>();
    k_count_deg<<<GB_E, TPB>>>(dst);
    k_amp_att<<<GB_N, TPB>>>(avg_dl);

    // embeddings
    gemm128_kernel<<<NB_N, 256>>>(PlainLd{x_in, FF}, StoreEp{p_x}, node_emb_w, node_emb_b, NN, FF);
    gemm128_kernel<<<NB_E, 256>>>(PlainLd{edge_attr, EDD}, StoreEp{p_ea}, edge_emb_w, edge_emb_b, EE, EDD);
    gemm128_kernel<<<NB_EP, 256>>>(PlainLd{pos_attr, EDD}, StoreEp{pos_out}, edge_emb_w, edge_emb_b, EPP, EDD);
    gemm128_kernel<<<NB_EP, 256>>>(PlainLd{neg_attr, EDD}, StoreEp{neg_out}, edge_emb_w, edge_emb_b, EPP, EDD);

    for (int l = 0; l < LL; l++) {
        const float* eW  = eenc_w  + (long)l * HH * HH;
        const float* eB  = eenc_b  + (long)l * HH;
        const float* pW  = pre_w   + (long)l * 3 * HH * HH;
        const float* pB  = pre_b   + (long)l * HH;
        const float* poW = post_w  + (long)l * 13 * HH * HH;
        const float* poB = post_b  + (long)l * HH;
        const float* lW  = lin_w   + (long)l * HH * HH;
        const float* lB  = lin_b   + (long)l * HH;
        const float* m1W = emlp_w1 + (long)l * 3 * HH * HH;
        const float* m1B = emlp_b1 + (long)l * HH;
        const float* m2W = emlp_w2 + (long)l * HH * HH;
        const float* m2B = emlp_b2 + (long)l * HH;
        const float* bG  = bn_g    + (long)l * HH;
        const float* bB  = bn_b    + (long)l * HH;

        k_init_agg<<<GB_NH, TPB>>>();
        k_zero_bn<<<1, HH>>>();

        // e_enc = ea @ eenc_w + b
        gemm128_kernel<<<NB_E, 256>>>(PlainLd{p_ea, HH}, StoreEp{p_eenc}, eW, eB, EE, HH);

        // h = [x[dst], x[src], e_enc] @ pre_w + b   (fused segment agg epilogue)
        gemm128_kernel<<<NB_E, 256>>>(GatherLd{p_x, dst, src, p_eenc},
                                      AggEp{p_s1, p_s2, p_mn, p_mx, dst}, pW, pB, EE, 3 * HH);

        k_fin_agg<<<GB_NH, TPB>>>();

        // out = [x, agg, agg*amp, agg*att] @ post_w + b
        gemm128_kernel<<<NB_N, 256>>>(PostLd{p_x, p_s1, p_mn, p_mx, p_s2, p_amp, p_att},
                                      StoreEp{p_post}, poW, poB, NN, 13 * HH);
        // out = out @ lin_w + b
        gemm128_kernel<<<NB_N, 256>>>(PlainLd{p_post, HH}, StoreEp{p_lin}, lW, lB, NN, HH);

        k_bn_stats<<<256, HH>>>(p_lin);
        k_bn_fin<<<1, HH>>>();
        k_apply<<<GB_NH, TPB>>>(bG, bB);

        // upd = relu([x[src], x[dst], ea] @ emlp_w1 + b1)
        gemm128_kernel<<<NB_E, 256>>>(GatherLd{p_x, src, dst, p_ea},
                                      ReluEp{p_upd}, m1W, m1B, EE, 3 * HH);
        // ea = ea + (upd @ emlp_w2 + b2) / 2
        gemm128_kernel<<<NB_E, 256>>>(PlainLd{p_upd, HH}, EaEp{p_ea}, m2W, m2B, EE, HH);
    }

    k_copy_x<<<GB_NH, TPB>>>(out);
}

// round 4
// speedup vs baseline: 3.9522x; 2.3194x over previous
#include <cuda_runtime.h>
#include <cstdint>
#include <math.h>

#define NN 50000
#define EE 400000
#define EPP 40000
#define FF 64
#define EDD 32
#define HH 128
#define LL 2

// ---------------- scratch (device globals; no allocation allowed) ----------------
__device__ float g_x[NN * HH];
__device__ float g_ea[EE * HH];
__device__ float g_eenc[EE * HH];
__device__ float g_upd[EE * HH];
__device__ float g_post[NN * HH];
__device__ float g_lin[NN * HH];
__device__ float g_s1[NN * HH];   // becomes mean after finalize
__device__ float g_s2[NN * HH];   // becomes std after finalize
__device__ float g_mn[NN * HH];
__device__ float g_mx[NN * HH];
__device__ int   g_deg[NN];
__device__ float g_amp[NN];
__device__ float g_att[NN];
__device__ float g_bnsum[HH];
__device__ float g_bnsq[HH];
__device__ float g_bnmu[HH];
__device__ float g_bnrstd[HH];

// ---------------- helpers ----------------
__device__ __forceinline__ uint32_t f2tf32(float x) {
    uint32_t r; asm("cvt.rn.tf32.f32 %0, %1;" : "=r"(r) : "f"(x)); return r;
}
__device__ __forceinline__ void mma_tf32(float c[4], const uint32_t a[4], const uint32_t b[2]) {
    asm volatile(
        "mma.sync.aligned.m16n8k8.row.col.f32.tf32.tf32.f32 "
        "{%0,%1,%2,%3}, {%4,%5,%6,%7}, {%8,%9}, {%0,%1,%2,%3};\n"
        : "+f"(c[0]), "+f"(c[1]), "+f"(c[2]), "+f"(c[3])
        : "r"(a[0]), "r"(a[1]), "r"(a[2]), "r"(a[3]), "r"(b[0]), "r"(b[1]));
}

// ---------------- atomic float min/max ----------------
__device__ __forceinline__ void atomicMaxF(float* a, float v) {
    if (v >= 0.f) atomicMax((int*)a, __float_as_int(v));
    else          atomicMin((unsigned int*)a, __float_as_uint(v));
}
__device__ __forceinline__ void atomicMinF(float* a, float v) {
    if (v >= 0.f) atomicMin((int*)a, __float_as_int(v));
    else          atomicMax((unsigned int*)a, __float_as_uint(v));
}

// ---------------- A-tile loaders (load4: 4 consecutive k, k%4==0, K%16==0) ----------------
struct PlainLd {
    const float* __restrict__ A; int K;
    __device__ __forceinline__ float4 load4(int r, int k) const {
        return *(const float4*)(A + (long)r * K + k);
    }
};
struct GatherLd {  // [x[i0[r]], x[i1[r]], third[r]]  (each 128 wide)
    const float* __restrict__ x;
    const int* __restrict__ i0;
    const int* __restrict__ i1;
    const float* __restrict__ third;
    __device__ __forceinline__ float4 load4(int r, int k) const {
        if (k < 128) return *(const float4*)(x + (long)i0[r] * 128 + k);
        if (k < 256) return *(const float4*)(x + (long)i1[r] * 128 + (k - 128));
        return *(const float4*)(third + (long)r * 128 + (k - 256));
    }
};
struct PostLd {  // [x, agg, agg*amp, agg*att]; agg = [mean, mn, mx, std]
    const float* __restrict__ x;
    const float* __restrict__ mean;
    const float* __restrict__ mn;
    const float* __restrict__ mx;
    const float* __restrict__ sd;
    const float* __restrict__ amp;
    const float* __restrict__ att;
    __device__ __forceinline__ float4 load4(int r, int k) const {
        if (k < 128) return *(const float4*)(x + (long)r * 128 + k);
        int jj  = k - 128;
        int grp = jj >> 9;        // 0: raw, 1: *amp, 2: *att
        int rem = jj & 511;
        int a   = rem >> 7;       // 0 mean, 1 mn, 2 mx, 3 std
        int c   = rem & 127;
        const float* base = (a == 0) ? mean : (a == 1) ? mn : (a == 2) ? mx : sd;
        float4 v = *(const float4*)(base + (long)r * 128 + c);
        float s = (grp == 1) ? amp[r] : (grp == 2) ? att[r] : 1.f;
        v.x *= s; v.y *= s; v.z *= s; v.w *= s;
        return v;
    }
};

// ---------------- epilogues: pair(row, col, v0, v1) writes cols col, col+1 ----------------
struct StoreEp {
    float* __restrict__ o;
    __device__ __forceinline__ void pair(int r, int c, float v0, float v1) const {
        *(float2*)(o + (long)r * 128 + c) = make_float2(v0, v1);
    }
};
struct ReluEp {
    float* __restrict__ o;
    __device__ __forceinline__ void pair(int r, int c, float v0, float v1) const {
        *(float2*)(o + (long)r * 128 + c) = make_float2(fmaxf(v0, 0.f), fmaxf(v1, 0.f));
    }
};
struct EaEp {  // ea += v/2
    float* __restrict__ ea;
    __device__ __forceinline__ void pair(int r, int c, float v0, float v1) const {
        float2* p = (float2*)(ea + (long)r * 128 + c);
        float2 cur = *p;
        cur.x += 0.5f * v0; cur.y += 0.5f * v1;
        *p = cur;
    }
};
struct AggEp {  // segment sum / sumsq / min / max over dst
    float* __restrict__ s1; float* __restrict__ s2;
    float* __restrict__ mn; float* __restrict__ mx;
    const int* __restrict__ dst;
    __device__ __forceinline__ void one(long o, float v) const {
        atomicAdd(s1 + o, v);
        atomicAdd(s2 + o, v * v);
        atomicMaxF(mx + o, v);
        atomicMinF(mn + o, v);
    }
    __device__ __forceinline__ void pair(int r, int c, float v0, float v1) const {
        long o = (long)dst[r] * 128 + c;
        one(o, v0);
        one(o + 1, v1);
    }
};

// ---------------- tensor-core GEMM: out[M,128] = A[M,K] @ W[K,128] + b ----------------
// 128x128 CTA tile, 256 threads = 8 warps (4 M x 2 N), warp tile 32x64.
// mma.sync m16n8k8 tf32. K chunk = 16.
#define KT 16
#define AP 20    // A row pitch (floats): conflict-free for fragment reads
#define WP 132   // W row pitch (floats)

template <typename Loader, typename Epi>
__global__ void __launch_bounds__(256, 2) gemm_mma(
    Loader ld, Epi ep,
    const float* __restrict__ W, const float* __restrict__ bias,
    int M, int K)
{
    __shared__ float As[128 * AP];
    __shared__ float Ws[KT * WP];
    const int tid  = threadIdx.x;
    const int lane = tid & 31;
    const int wid  = tid >> 5;
    const int wm   = wid & 3;        // warp row: 32 rows each
    const int wn   = wid >> 2;       // warp col: 64 cols each
    const int gid  = lane >> 2;      // 0..7
    const int tid4 = lane & 3;       // 0..3
    const int row0 = blockIdx.x * 128;

    float acc[2][8][4];
#pragma unroll
    for (int mt = 0; mt < 2; mt++)
#pragma unroll
        for (int nt = 0; nt < 8; nt++)
#pragma unroll
            for (int i = 0; i < 4; i++) acc[mt][nt][i] = 0.f;

    for (int k0 = 0; k0 < K; k0 += KT) {
        // stage A tile: 128 rows x 16 k (cvt to tf32)
#pragma unroll
        for (int i = 0; i < 2; i++) {
            int f = tid + 256 * i;       // 0..511 float4 slots
            int r = f >> 2, q = f & 3;
            int grow = row0 + r;
            float4 v = make_float4(0.f, 0.f, 0.f, 0.f);
            if (grow < M) v = ld.load4(grow, k0 + q * 4);
            float* d = &As[r * AP + q * 4];
            d[0] = __uint_as_float(f2tf32(v.x));
            d[1] = __uint_as_float(f2tf32(v.y));
            d[2] = __uint_as_float(f2tf32(v.z));
            d[3] = __uint_as_float(f2tf32(v.w));
        }
        // stage W tile: 16 k x 128 n (cvt to tf32)
#pragma unroll
        for (int i = 0; i < 2; i++) {
            int f = tid + 256 * i;       // 0..511
            int k = f >> 5, c4 = f & 31;
            float4 v = *(const float4*)&W[(long)(k0 + k) * 128 + c4 * 4];
            float* d = &Ws[k * WP + c4 * 4];
            d[0] = __uint_as_float(f2tf32(v.x));
            d[1] = __uint_as_float(f2tf32(v.y));
            d[2] = __uint_as_float(f2tf32(v.z));
            d[3] = __uint_as_float(f2tf32(v.w));
        }
        __syncthreads();

#pragma unroll
        for (int ks = 0; ks < KT; ks += 8) {
            uint32_t a[2][4];
#pragma unroll
            for (int mt = 0; mt < 2; mt++) {
                int m0 = wm * 32 + mt * 16;
                a[mt][0] = __float_as_uint(As[(m0 + gid) * AP + ks + tid4]);
                a[mt][1] = __float_as_uint(As[(m0 + 8 + gid) * AP + ks + tid4]);
                a[mt][2] = __float_as_uint(As[(m0 + gid) * AP + ks + tid4 + 4]);
                a[mt][3] = __float_as_uint(As[(m0 + 8 + gid) * AP + ks + tid4 + 4]);
            }
            uint32_t b[8][2];
#pragma unroll
            for (int nt = 0; nt < 8; nt++) {
                int n = wn * 64 + nt * 8 + gid;
                b[nt][0] = __float_as_uint(Ws[(ks + tid4) * WP + n]);
                b[nt][1] = __float_as_uint(Ws[(ks + tid4 + 4) * WP + n]);
            }
#pragma unroll
            for (int mt = 0; mt < 2; mt++)
#pragma unroll
                for (int nt = 0; nt < 8; nt++)
                    mma_tf32(acc[mt][nt], a[mt], b[nt]);
        }
        __syncthreads();
    }

    // epilogue: C fragment c0,c1 -> (row gid, cols 2*tid4+{0,1}), c2,c3 -> row gid+8
    float bv[8][2];
#pragma unroll
    for (int nt = 0; nt < 8; nt++) {
        int c = wn * 64 + nt * 8 + 2 * tid4;
        bv[nt][0] = bias[c];
        bv[nt][1] = bias[c + 1];
    }
#pragma unroll
    for (int mt = 0; mt < 2; mt++) {
        int rA = row0 + wm * 32 + mt * 16 + gid;
        int rB = rA + 8;
#pragma unroll
        for (int nt = 0; nt < 8; nt++) {
            int c = wn * 64 + nt * 8 + 2 * tid4;
            if (rA < M) ep.pair(rA, c, acc[mt][nt][0] + bv[nt][0], acc[mt][nt][1] + bv[nt][1]);
            if (rB < M) ep.pair(rB, c, acc[mt][nt][2] + bv[nt][0], acc[mt][nt][3] + bv[nt][1]);
        }
    }
}

// ---------------- small kernels ----------------
__global__ void k_zero_deg() {
    int i = blockIdx.x * blockDim.x + threadIdx.x;
    if (i < NN) g_deg[i] = 0;
}
__global__ void k_count_deg(const int* __restrict__ dst) {
    int e = blockIdx.x * blockDim.x + threadIdx.x;
    if (e < EE) atomicAdd(&g_deg[dst[e]], 1);
}
__global__ void k_amp_att(const float* __restrict__ adl) {
    int i = blockIdx.x * blockDim.x + threadIdx.x;
    if (i < NN) {
        float d = fmaxf((float)g_deg[i], 1.f);
        float lg = logf(d + 1.f);
        float a = adl[0];
        g_amp[i] = lg / a;
        g_att[i] = a / lg;
    }
}
__global__ void k_init_agg() {
    long i = (long)blockIdx.x * blockDim.x + threadIdx.x;
    if (i < (long)NN * HH) {
        g_s1[i] = 0.f;
        g_s2[i] = 0.f;
        g_mn[i] = __int_as_float(0x7f800000);   // +inf
        g_mx[i] = __int_as_float(0xff800000);   // -inf
    }
}
__global__ void k_zero_bn() {
    int c = threadIdx.x;
    g_bnsum[c] = 0.f;
    g_bnsq[c] = 0.f;
}
__global__ void k_fin_agg() {
    long i = (long)blockIdx.x * blockDim.x + threadIdx.x;
    if (i < (long)NN * HH) {
        int n = (int)(i >> 7);
        int d = g_deg[n];
        float degc = fmaxf((float)d, 1.f);
        float m = g_s1[i] / degc;
        float var = g_s2[i] / degc - m * m;
        g_s1[i] = m;
        g_s2[i] = sqrtf(fmaxf(var, 0.f) + 1e-5f);
        if (d == 0) { g_mn[i] = 0.f; g_mx[i] = 0.f; }
    }
}
__global__ void k_bn_stats(const float* __restrict__ o) {
    int c = threadIdx.x;           // 128 threads
    float s = 0.f, s2 = 0.f;
    for (int r = blockIdx.x; r < NN; r += gridDim.x) {
        float v = o[(long)r * 128 + c];
        s += v; s2 += v * v;
    }
    atomicAdd(&g_bnsum[c], s);
    atomicAdd(&g_bnsq[c], s2);
}
__global__ void k_bn_fin() {
    int c = threadIdx.x;
    float mu = g_bnsum[c] / (float)NN;
    float var = g_bnsq[c] / (float)NN - mu * mu;
    g_bnmu[c] = mu;
    g_bnrstd[c] = rsqrtf(var + 1e-5f);
}
__global__ void k_apply(const float* __restrict__ bng, const float* __restrict__ bnb) {
    long i = (long)blockIdx.x * blockDim.x + threadIdx.x;
    if (i < (long)NN * HH) {
        int c = (int)(i & 127);
        float v = bng[c] * (g_lin[i] - g_bnmu[c]) * g_bnrstd[c] + bnb[c];
        g_x[i] = (g_x[i] + fmaxf(v, 0.f)) * 0.5f;
    }
}
__global__ void k_copy_x(float* __restrict__ o) {
    long i = (long)blockIdx.x * blockDim.x + threadIdx.x;
    if (i < (long)NN * HH) o[i] = g_x[i];
}

// ---------------- launch ----------------
extern "C" void kernel_launch(void* const* d_in, const int* in_sizes, int n_in,
                              void* d_out, int out_size) {
    const float* x_in       = (const float*)d_in[0];
    const int*   eidx       = (const int*)  d_in[1];
    const float* edge_attr  = (const float*)d_in[2];
    const float* pos_attr   = (const float*)d_in[4];
    const float* neg_attr   = (const float*)d_in[6];
    const float* avg_dl     = (const float*)d_in[7];
    const float* node_emb_w = (const float*)d_in[8];
    const float* node_emb_b = (const float*)d_in[9];
    const float* edge_emb_w = (const float*)d_in[10];
    const float* edge_emb_b = (const float*)d_in[11];
    const float* eenc_w     = (const float*)d_in[12];
    const float* eenc_b     = (const float*)d_in[13];
    const float* pre_w      = (const float*)d_in[14];
    const float* pre_b      = (const float*)d_in[15];
    const float* post_w     = (const float*)d_in[16];
    const float* post_b     = (const float*)d_in[17];
    const float* lin_w      = (const float*)d_in[18];
    const float* lin_b      = (const float*)d_in[19];
    const float* emlp_w1    = (const float*)d_in[20];
    const float* emlp_b1    = (const float*)d_in[21];
    const float* emlp_w2    = (const float*)d_in[22];
    const float* emlp_b2    = (const float*)d_in[23];
    const float* bn_g       = (const float*)d_in[24];
    const float* bn_b       = (const float*)d_in[25];

    const int* src = eidx;          // edge_index[0]
    const int* dst = eidx + EE;     // edge_index[1]

    float* out     = (float*)d_out;
    float* pos_out = out + (long)NN * HH;
    float* neg_out = pos_out + (long)EPP * HH;

    float *p_x, *p_ea, *p_eenc, *p_upd, *p_post, *p_lin, *p_s1, *p_s2, *p_mn, *p_mx, *p_amp, *p_att;
    cudaGetSymbolAddress((void**)&p_x, g_x);
    cudaGetSymbolAddress((void**)&p_ea, g_ea);
    cudaGetSymbolAddress((void**)&p_eenc, g_eenc);
    cudaGetSymbolAddress((void**)&p_upd, g_upd);
    cudaGetSymbolAddress((void**)&p_post, g_post);
    cudaGetSymbolAddress((void**)&p_lin, g_lin);
    cudaGetSymbolAddress((void**)&p_s1, g_s1);
    cudaGetSymbolAddress((void**)&p_s2, g_s2);
    cudaGetSymbolAddress((void**)&p_mn, g_mn);
    cudaGetSymbolAddress((void**)&p_mx, g_mx);
    cudaGetSymbolAddress((void**)&p_amp, g_amp);
    cudaGetSymbolAddress((void**)&p_att, g_att);

    const int NB_N  = (NN + 127) / 128;      // 391
    const int NB_E  = (EE + 127) / 128;      // 3125
    const int NB_EP = (EPP + 127) / 128;     // 313
    const int TPB = 256;
    const int GB_N = (NN + TPB - 1) / TPB;
    const int GB_E = (EE + TPB - 1) / TPB;
    const long NH = (long)NN * HH;
    const int GB_NH = (int)((NH + TPB - 1) / TPB);

    // degree + amp/att (static over layers)
    k_zero_deg<<<GB_N, TPB>>>();
    k_count_deg<<<GB_E, TPB>>>(dst);
    k_amp_att<<<GB_N, TPB>>>(avg_dl);

    // embeddings
    gemm_mma<<<NB_N, 256>>>(PlainLd{x_in, FF}, StoreEp{p_x}, node_emb_w, node_emb_b, NN, FF);
    gemm_mma<<<NB_E, 256>>>(PlainLd{edge_attr, EDD}, StoreEp{p_ea}, edge_emb_w, edge_emb_b, EE, EDD);
    gemm_mma<<<NB_EP, 256>>>(PlainLd{pos_attr, EDD}, StoreEp{pos_out}, edge_emb_w, edge_emb_b, EPP, EDD);
    gemm_mma<<<NB_EP, 256>>>(PlainLd{neg_attr, EDD}, StoreEp{neg_out}, edge_emb_w, edge_emb_b, EPP, EDD);

    for (int l = 0; l < LL; l++) {
        const float* eW  = eenc_w  + (long)l * HH * HH;
        const float* eB  = eenc_b  + (long)l * HH;
        const float* pW  = pre_w   + (long)l * 3 * HH * HH;
        const float* pB  = pre_b   + (long)l * HH;
        const float* poW = post_w  + (long)l * 13 * HH * HH;
        const float* poB = post_b  + (long)l * HH;
        const float* lW  = lin_w   + (long)l * HH * HH;
        const float* lB  = lin_b   + (long)l * HH;
        const float* m1W = emlp_w1 + (long)l * 3 * HH * HH;
        const float* m1B = emlp_b1 + (long)l * HH;
        const float* m2W = emlp_w2 + (long)l * HH * HH;
        const float* m2B = emlp_b2 + (long)l * HH;
        const float* bG  = bn_g    + (long)l * HH;
        const float* bB  = bn_b    + (long)l * HH;

        k_init_agg<<<GB_NH, TPB>>>();
        k_zero_bn<<<1, HH>>>();

        // e_enc = ea @ eenc_w + b
        gemm_mma<<<NB_E, 256>>>(PlainLd{p_ea, HH}, StoreEp{p_eenc}, eW, eB, EE, HH);

        // h = [x[dst], x[src], e_enc] @ pre_w + b   (fused segment agg epilogue)
        gemm_mma<<<NB_E, 256>>>(GatherLd{p_x, dst, src, p_eenc},
                                AggEp{p_s1, p_s2, p_mn, p_mx, dst}, pW, pB, EE, 3 * HH);

        k_fin_agg<<<GB_NH, TPB>>>();

        // out = [x, agg, agg*amp, agg*att] @ post_w + b
        gemm_mma<<<NB_N, 256>>>(PostLd{p_x, p_s1, p_mn, p_mx, p_s2, p_amp, p_att},
                                StoreEp{p_post}, poW, poB, NN, 13 * HH);
        // out = out @ lin_w + b
        gemm_mma<<<NB_N, 256>>>(PlainLd{p_post, HH}, StoreEp{p_lin}, lW, lB, NN, HH);

        k_bn_stats<<<256, HH>>>(p_lin);
        k_bn_fin<<<1, HH>>>();
        k_apply<<<GB_NH, TPB>>>(bG, bB);

        // upd = relu([x[src], x[dst], ea] @ emlp_w1 + b1)
        gemm_mma<<<NB_E, 256>>>(GatherLd{p_x, src, dst, p_ea},
                                ReluEp{p_upd}, m1W, m1B, EE, 3 * HH);
        // ea = ea + (upd @ emlp_w2 + b2) / 2
        gemm_mma<<<NB_E, 256>>>(PlainLd{p_upd, HH}, EaEp{p_ea}, m2W, m2B, EE, HH);
    }

    k_copy_x<<<GB_NH, TPB>>>(out);
}

// round 5
// speedup vs baseline: 5.5002x; 1.3917x over previous
#include <cuda_runtime.h>
#include <cstdint>
#include <math.h>

#define NN 50000
#define EE 400000
#define EPP 40000
#define FF 64
#define EDD 32
#define HH 128
#define LL 2

// ---------------- scratch (device globals; no allocation allowed) ----------------
__device__ float g_x[NN * HH];
__device__ float g_ea[EE * HH];
__device__ float g_eenc[EE * HH];
__device__ float g_upd[EE * HH];
__device__ float g_post[NN * HH];
__device__ float g_lin[NN * HH];
__device__ float g_s1[NN * HH];   // becomes mean after finalize
__device__ float g_s2[NN * HH];   // becomes std after finalize
__device__ float g_mn[NN * HH];
__device__ float g_mx[NN * HH];
__device__ int   g_deg[NN];
__device__ float g_amp[NN];
__device__ float g_att[NN];
__device__ float g_bnsum[HH];
__device__ float g_bnsq[HH];
__device__ float g_bnmu[HH];
__device__ float g_bnrstd[HH];

// ---------------- helpers ----------------
__device__ __forceinline__ uint32_t smem_u32(const void* p) {
    uint32_t a;
    asm("{ .reg .u64 t; cvta.to.shared.u64 t, %1; cvt.u32.u64 %0, t; }" : "=r"(a) : "l"(p));
    return a;
}
__device__ __forceinline__ uint32_t f2tf32(float x) {
    uint32_t r; asm("cvt.rn.tf32.f32 %0, %1;" : "=r"(r) : "f"(x)); return r;
}
__device__ __forceinline__ void cp16(uint32_t sdst, const void* gsrc, bool full) {
    int sz = full ? 16 : 0;
    asm volatile("cp.async.cg.shared.global [%0], [%1], 16, %2;"
                 :: "r"(sdst), "l"(gsrc), "r"(sz) : "memory");
}
__device__ __forceinline__ void cp_commit() {
    asm volatile("cp.async.commit_group;" ::: "memory");
}
__device__ __forceinline__ void mma_tf32(float c[4], const uint32_t a[4], const uint32_t b[2]) {
    asm volatile(
        "mma.sync.aligned.m16n8k8.row.col.f32.tf32.tf32.f32 "
        "{%0,%1,%2,%3}, {%4,%5,%6,%7}, {%8,%9}, {%0,%1,%2,%3};\n"
        : "+f"(c[0]), "+f"(c[1]), "+f"(c[2]), "+f"(c[3])
        : "r"(a[0]), "r"(a[1]), "r"(a[2]), "r"(a[3]), "r"(b[0]), "r"(b[1]));
}

// ---------------- atomic float min/max ----------------
__device__ __forceinline__ void atomicMaxF(float* a, float v) {
    if (v >= 0.f) atomicMax((int*)a, __float_as_int(v));
    else          atomicMin((unsigned int*)a, __float_as_uint(v));
}
__device__ __forceinline__ void atomicMinF(float* a, float v) {
    if (v >= 0.f) atomicMin((int*)a, __float_as_int(v));
    else          atomicMax((unsigned int*)a, __float_as_uint(v));
}

// ---------------- A-tile loaders: ptr4(r,k) -> gmem pointer to 4 floats ----------------
// Chunk size KT=16; all concat/group boundaries are multiples of 16, so group
// selection is constant within a chunk.
struct PlainLd {
    const float* __restrict__ A; int K;
    static constexpr bool scaled = false;
    __device__ __forceinline__ const float* ptr4(int r, int k) const {
        return A + (long)r * K + k;
    }
    __device__ __forceinline__ float rowscale(int, int) const { return 1.f; }
};
struct GatherLd {  // [x[i0[r]], x[i1[r]], third[r]]  (each 128 wide)
    const float* __restrict__ x;
    const int* __restrict__ i0;
    const int* __restrict__ i1;
    const float* __restrict__ third;
    static constexpr bool scaled = false;
    __device__ __forceinline__ const float* ptr4(int r, int k) const {
        if (k < 128) return x + (long)i0[r] * 128 + k;
        if (k < 256) return x + (long)i1[r] * 128 + (k - 128);
        return third + (long)r * 128 + (k - 256);
    }
    __device__ __forceinline__ float rowscale(int, int) const { return 1.f; }
};
struct PostLd {  // [x, agg, agg*amp, agg*att]; agg = [mean, mn, mx, std]
    const float* __restrict__ x;
    const float* __restrict__ mean;
    const float* __restrict__ mn;
    const float* __restrict__ mx;
    const float* __restrict__ sd;
    const float* __restrict__ amp;
    const float* __restrict__ att;
    static constexpr bool scaled = true;
    __device__ __forceinline__ const float* ptr4(int r, int k) const {
        if (k < 128) return x + (long)r * 128 + k;
        int rem = (k - 128) & 511;
        int a   = rem >> 7;       // 0 mean, 1 mn, 2 mx, 3 std
        int c   = rem & 127;
        const float* base = (a == 0) ? mean : (a == 1) ? mn : (a == 2) ? mx : sd;
        return base + (long)r * 128 + c;
    }
    __device__ __forceinline__ float rowscale(int r, int k) const {
        if (k < 128) return 1.f;
        int grp = (k - 128) >> 9;   // 0: raw, 1: *amp, 2: *att
        return (grp == 1) ? amp[r] : (grp == 2) ? att[r] : 1.f;
    }
};

// ---------------- epilogues: pair(row, col, v0, v1) writes cols col, col+1 ----------------
struct StoreEp {
    float* __restrict__ o;
    __device__ __forceinline__ void pair(int r, int c, float v0, float v1) const {
        *(float2*)(o + (long)r * 128 + c) = make_float2(v0, v1);
    }
};
struct ReluEp {
    float* __restrict__ o;
    __device__ __forceinline__ void pair(int r, int c, float v0, float v1) const {
        *(float2*)(o + (long)r * 128 + c) = make_float2(fmaxf(v0, 0.f), fmaxf(v1, 0.f));
    }
};
struct EaEp {  // ea += v/2
    float* __restrict__ ea;
    __device__ __forceinline__ void pair(int r, int c, float v0, float v1) const {
        float2* p = (float2*)(ea + (long)r * 128 + c);
        float2 cur = *p;
        cur.x += 0.5f * v0; cur.y += 0.5f * v1;
        *p = cur;
    }
};
struct AggEp {  // segment sum / sumsq / min / max over dst
    float* __restrict__ s1; float* __restrict__ s2;
    float* __restrict__ mn; float* __restrict__ mx;
    const int* __restrict__ dst;
    __device__ __forceinline__ void one(long o, float v) const {
        atomicAdd(s1 + o, v);
        atomicAdd(s2 + o, v * v);
        atomicMaxF(mx + o, v);
        atomicMinF(mn + o, v);
    }
    __device__ __forceinline__ void pair(int r, int c, float v0, float v1) const {
        long o = (long)dst[r] * 128 + c;
        one(o, v0);
        one(o + 1, v1);
    }
};

// ---------------- tensor-core GEMM: out[M,128] = A[M,K] @ W[K,128] + b ----------------
// 128x128 CTA tile, 256 threads = 8 warps (4 M x 2 N), warp tile 32x64.
// mma.sync m16n8k8 tf32. K chunk = 16, cp.async 2-stage double buffer.
#define KT 16
#define AP 20    // A row pitch (floats): conflict-free for fragment reads
#define WP 136   // W row pitch (floats): conflict-free for fragment reads

template <typename Loader, typename Epi>
__global__ void __launch_bounds__(256, 2) gemm_mma(
    Loader ld, Epi ep,
    const float* __restrict__ W, const float* __restrict__ bias,
    int M, int K)
{
    __shared__ float As[2][128 * AP];
    __shared__ float Ws[2][KT * WP];
    const int tid  = threadIdx.x;
    const int lane = tid & 31;
    const int wid  = tid >> 5;
    const int wm   = wid & 3;        // warp row: 32 rows each
    const int wn   = wid >> 2;       // warp col: 64 cols each
    const int gid  = lane >> 2;      // 0..7
    const int tid4 = lane & 3;       // 0..3
    const int row0 = blockIdx.x * 128;

    // staging coordinates (2 x 16B per array per thread)
    const int sr0 = tid >> 2,  sq0 = tid & 3;            // A slot 0: row, quad
    const int sr1 = sr0 + 64;                            // A slot 1
    const int wk0 = tid >> 5,  wc0 = tid & 31;           // W slot 0: k, col4
    const int wk1 = wk0 + 8;                             // W slot 1

    const uint32_t sA = smem_u32(&As[0][0]);
    const uint32_t sW = smem_u32(&Ws[0][0]);

    float acc[2][8][4];
#pragma unroll
    for (int mt = 0; mt < 2; mt++)
#pragma unroll
        for (int nt = 0; nt < 8; nt++)
#pragma unroll
            for (int i = 0; i < 4; i++) acc[mt][nt][i] = 0.f;

    const int nch = K / KT;

    auto stage = [&](int buf, int k0) {
        uint32_t a_base = sA + buf * (128 * AP * 4);
        uint32_t w_base = sW + buf * (KT * WP * 4);
        int g0 = row0 + sr0, g1 = row0 + sr1;
        bool v0 = g0 < M, v1 = g1 < M;
        cp16(a_base + (sr0 * AP + sq0 * 4) * 4, ld.ptr4(v0 ? g0 : 0, k0 + sq0 * 4), v0);
        cp16(a_base + (sr1 * AP + sq0 * 4) * 4, ld.ptr4(v1 ? g1 : 0, k0 + sq0 * 4), v1);
        cp16(w_base + (wk0 * WP + wc0 * 4) * 4, W + (long)(k0 + wk0) * 128 + wc0 * 4, true);
        cp16(w_base + (wk1 * WP + wc0 * 4) * 4, W + (long)(k0 + wk1) * 128 + wc0 * 4, true);
        cp_commit();
    };

    stage(0, 0);

    for (int ch = 0; ch < nch; ch++) {
        const int buf = ch & 1;
        const int k0 = ch * KT;
        if (ch + 1 < nch) {
            stage(buf ^ 1, k0 + KT);
            asm volatile("cp.async.wait_group 1;" ::: "memory");
        } else {
            asm volatile("cp.async.wait_group 0;" ::: "memory");
        }
        __syncthreads();

        // per-chunk row scales (PostLd only)
        float rs[2][2];
        if constexpr (Loader::scaled) {
#pragma unroll
            for (int mt = 0; mt < 2; mt++) {
                int m0 = row0 + wm * 32 + mt * 16;
                int rA = m0 + gid, rB = m0 + 8 + gid;
                rs[mt][0] = ld.rowscale(rA < M ? rA : 0, k0);
                rs[mt][1] = ld.rowscale(rB < M ? rB : 0, k0);
            }
        }

        const float* Ab = &As[buf][0];
        const float* Wb = &Ws[buf][0];
#pragma unroll
        for (int ks = 0; ks < KT; ks += 8) {
            uint32_t a[2][4];
#pragma unroll
            for (int mt = 0; mt < 2; mt++) {
                int m0 = wm * 32 + mt * 16;
                float a0 = Ab[(m0 + gid) * AP + ks + tid4];
                float a1 = Ab[(m0 + 8 + gid) * AP + ks + tid4];
                float a2 = Ab[(m0 + gid) * AP + ks + tid4 + 4];
                float a3 = Ab[(m0 + 8 + gid) * AP + ks + tid4 + 4];
                if constexpr (Loader::scaled) {
                    a0 *= rs[mt][0]; a1 *= rs[mt][1];
                    a2 *= rs[mt][0]; a3 *= rs[mt][1];
                }
                a[mt][0] = f2tf32(a0); a[mt][1] = f2tf32(a1);
                a[mt][2] = f2tf32(a2); a[mt][3] = f2tf32(a3);
            }
            uint32_t b[8][2];
#pragma unroll
            for (int nt = 0; nt < 8; nt++) {
                int n = wn * 64 + nt * 8 + gid;
                b[nt][0] = f2tf32(Wb[(ks + tid4) * WP + n]);
                b[nt][1] = f2tf32(Wb[(ks + tid4 + 4) * WP + n]);
            }
#pragma unroll
            for (int mt = 0; mt < 2; mt++)
#pragma unroll
                for (int nt = 0; nt < 8; nt++)
                    mma_tf32(acc[mt][nt], a[mt], b[nt]);
        }
        __syncthreads();
    }

    // epilogue: C fragment c0,c1 -> (row gid, cols 2*tid4+{0,1}), c2,c3 -> row gid+8
    float bv[8][2];
#pragma unroll
    for (int nt = 0; nt < 8; nt++) {
        int c = wn * 64 + nt * 8 + 2 * tid4;
        bv[nt][0] = bias[c];
        bv[nt][1] = bias[c + 1];
    }
#pragma unroll
    for (int mt = 0; mt < 2; mt++) {
        int rA = row0 + wm * 32 + mt * 16 + gid;
        int rB = rA + 8;
#pragma unroll
        for (int nt = 0; nt < 8; nt++) {
            int c = wn * 64 + nt * 8 + 2 * tid4;
            if (rA < M) ep.pair(rA, c, acc[mt][nt][0] + bv[nt][0], acc[mt][nt][1] + bv[nt][1]);
            if (rB < M) ep.pair(rB, c, acc[mt][nt][2] + bv[nt][0], acc[mt][nt][3] + bv[nt][1]);
        }
    }
}

// ---------------- small kernels ----------------
__global__ void k_zero_deg() {
    int i = blockIdx.x * blockDim.x + threadIdx.x;
    if (i < NN) g_deg[i] = 0;
}
__global__ void k_count_deg(const int* __restrict__ dst) {
    int e = blockIdx.x * blockDim.x + threadIdx.x;
    if (e < EE) atomicAdd(&g_deg[dst[e]], 1);
}
__global__ void k_amp_att(const float* __restrict__ adl) {
    int i = blockIdx.x * blockDim.x + threadIdx.x;
    if (i < NN) {
        float d = fmaxf((float)g_deg[i], 1.f);
        float lg = logf(d + 1.f);
        float a = adl[0];
        g_amp[i] = lg / a;
        g_att[i] = a / lg;
    }
}
__global__ void k_init_agg() {
    long i = (long)blockIdx.x * blockDim.x + threadIdx.x;
    if (i < (long)NN * HH) {
        g_s1[i] = 0.f;
        g_s2[i] = 0.f;
        g_mn[i] = __int_as_float(0x7f800000);   // +inf
        g_mx[i] = __int_as_float(0xff800000);   // -inf
    }
}
__global__ void k_zero_bn() {
    int c = threadIdx.x;
    g_bnsum[c] = 0.f;
    g_bnsq[c] = 0.f;
}
__global__ void k_fin_agg() {
    long i = (long)blockIdx.x * blockDim.x + threadIdx.x;
    if (i < (long)NN * HH) {
        int n = (int)(i >> 7);
        int d = g_deg[n];
        float degc = fmaxf((float)d, 1.f);
        float m = g_s1[i] / degc;
        float var = g_s2[i] / degc - m * m;
        g_s1[i] = m;
        g_s2[i] = sqrtf(fmaxf(var, 0.f) + 1e-5f);
        if (d == 0) { g_mn[i] = 0.f; g_mx[i] = 0.f; }
    }
}
__global__ void k_bn_stats(const float* __restrict__ o) {
    int c = threadIdx.x;           // 128 threads
    float s = 0.f, s2 = 0.f;
    for (int r = blockIdx.x; r < NN; r += gridDim.x) {
        float v = o[(long)r * 128 + c];
        s += v; s2 += v * v;
    }
    atomicAdd(&g_bnsum[c], s);
    atomicAdd(&g_bnsq[c], s2);
}
__global__ void k_bn_fin() {
    int c = threadIdx.x;
    float mu = g_bnsum[c] / (float)NN;
    float var = g_bnsq[c] / (float)NN - mu * mu;
    g_bnmu[c] = mu;
    g_bnrstd[c] = rsqrtf(var + 1e-5f);
}
__global__ void k_apply(const float* __restrict__ bng, const float* __restrict__ bnb) {
    long i = (long)blockIdx.x * blockDim.x + threadIdx.x;
    if (i < (long)NN * HH) {
        int c = (int)(i & 127);
        float v = bng[c] * (g_lin[i] - g_bnmu[c]) * g_bnrstd[c] + bnb[c];
        g_x[i] = (g_x[i] + fmaxf(v, 0.f)) * 0.5f;
    }
}
__global__ void k_copy_x(float* __restrict__ o) {
    long i = (long)blockIdx.x * blockDim.x + threadIdx.x;
    if (i < (long)NN * HH) o[i] = g_x[i];
}

// ---------------- launch ----------------
extern "C" void kernel_launch(void* const* d_in, const int* in_sizes, int n_in,
                              void* d_out, int out_size) {
    const float* x_in       = (const float*)d_in[0];
    const int*   eidx       = (const int*)  d_in[1];
    const float* edge_attr  = (const float*)d_in[2];
    const float* pos_attr   = (const float*)d_in[4];
    const float* neg_attr   = (const float*)d_in[6];
    const float* avg_dl     = (const float*)d_in[7];
    const float* node_emb_w = (const float*)d_in[8];
    const float* node_emb_b = (const float*)d_in[9];
    const float* edge_emb_w = (const float*)d_in[10];
    const float* edge_emb_b = (const float*)d_in[11];
    const float* eenc_w     = (const float*)d_in[12];
    const float* eenc_b     = (const float*)d_in[13];
    const float* pre_w      = (const float*)d_in[14];
    const float* pre_b      = (const float*)d_in[15];
    const float* post_w     = (const float*)d_in[16];
    const float* post_b     = (const float*)d_in[17];
    const float* lin_w      = (const float*)d_in[18];
    const float* lin_b      = (const float*)d_in[19];
    const float* emlp_w1    = (const float*)d_in[20];
    const float* emlp_b1    = (const float*)d_in[21];
    const float* emlp_w2    = (const float*)d_in[22];
    const float* emlp_b2    = (const float*)d_in[23];
    const float* bn_g       = (const float*)d_in[24];
    const float* bn_b       = (const float*)d_in[25];

    const int* src = eidx;          // edge_index[0]
    const int* dst = eidx + EE;     // edge_index[1]

    float* out     = (float*)d_out;
    float* pos_out = out + (long)NN * HH;
    float* neg_out = pos_out + (long)EPP * HH;

    float *p_x, *p_ea, *p_eenc, *p_upd, *p_post, *p_lin, *p_s1, *p_s2, *p_mn, *p_mx, *p_amp, *p_att;
    cudaGetSymbolAddress((void**)&p_x, g_x);
    cudaGetSymbolAddress((void**)&p_ea, g_ea);
    cudaGetSymbolAddress((void**)&p_eenc, g_eenc);
    cudaGetSymbolAddress((void**)&p_upd, g_upd);
    cudaGetSymbolAddress((void**)&p_post, g_post);
    cudaGetSymbolAddress((void**)&p_lin, g_lin);
    cudaGetSymbolAddress((void**)&p_s1, g_s1);
    cudaGetSymbolAddress((void**)&p_s2, g_s2);
    cudaGetSymbolAddress((void**)&p_mn, g_mn);
    cudaGetSymbolAddress((void**)&p_mx, g_mx);
    cudaGetSymbolAddress((void**)&p_amp, g_amp);
    cudaGetSymbolAddress((void**)&p_att, g_att);

    const int NB_N  = (NN + 127) / 128;      // 391
    const int NB_E  = (EE + 127) / 128;      // 3125
    const int NB_EP = (EPP + 127) / 128;     // 313
    const int TPB = 256;
    const int GB_N = (NN + TPB - 1) / TPB;
    const int GB_E = (EE + TPB - 1) / TPB;
    const long NH = (long)NN * HH;
    const int GB_NH = (int)((NH + TPB - 1) / TPB);

    // degree + amp/att (static over layers)
    k_zero_deg<<<GB_N, TPB>>>();
    k_count_deg<<<GB_E, TPB>>>(dst);
    k_amp_att<<<GB_N, TPB>>>(avg_dl);

    // embeddings
    gemm_mma<<<NB_N, 256>>>(PlainLd{x_in, FF}, StoreEp{p_x}, node_emb_w, node_emb_b, NN, FF);
    gemm_mma<<<NB_E, 256>>>(PlainLd{edge_attr, EDD}, StoreEp{p_ea}, edge_emb_w, edge_emb_b, EE, EDD);
    gemm_mma<<<NB_EP, 256>>>(PlainLd{pos_attr, EDD}, StoreEp{pos_out}, edge_emb_w, edge_emb_b, EPP, EDD);
    gemm_mma<<<NB_EP, 256>>>(PlainLd{neg_attr, EDD}, StoreEp{neg_out}, edge_emb_w, edge_emb_b, EPP, EDD);

    for (int l = 0; l < LL; l++) {
        const float* eW  = eenc_w  + (long)l * HH * HH;
        const float* eB  = eenc_b  + (long)l * HH;
        const float* pW  = pre_w   + (long)l * 3 * HH * HH;
        const float* pB  = pre_b   + (long)l * HH;
        const float* poW = post_w  + (long)l * 13 * HH * HH;
        const float* poB = post_b  + (long)l * HH;
        const float* lW  = lin_w   + (long)l * HH * HH;
        const float* lB  = lin_b   + (long)l * HH;
        const float* m1W = emlp_w1 + (long)l * 3 * HH * HH;
        const float* m1B = emlp_b1 + (long)l * HH;
        const float* m2W = emlp_w2 + (long)l * HH * HH;
        const float* m2B = emlp_b2 + (long)l * HH;
        const float* bG  = bn_g    + (long)l * HH;
        const float* bB  = bn_b    + (long)l * HH;

        k_init_agg<<<GB_NH, TPB>>>();
        k_zero_bn<<<1, HH>>>();

        // e_enc = ea @ eenc_w + b
        gemm_mma<<<NB_E, 256>>>(PlainLd{p_ea, HH}, StoreEp{p_eenc}, eW, eB, EE, HH);

        // h = [x[dst], x[src], e_enc] @ pre_w + b   (fused segment agg epilogue)
        gemm_mma<<<NB_E, 256>>>(GatherLd{p_x, dst, src, p_eenc},
                                AggEp{p_s1, p_s2, p_mn, p_mx, dst}, pW, pB, EE, 3 * HH);

        k_fin_agg<<<GB_NH, TPB>>>();

        // out = [x, agg, agg*amp, agg*att] @ post_w + b
        gemm_mma<<<NB_N, 256>>>(PostLd{p_x, p_s1, p_mn, p_mx, p_s2, p_amp, p_att},
                                StoreEp{p_post}, poW, poB, NN, 13 * HH);
        // out = out @ lin_w + b
        gemm_mma<<<NB_N, 256>>>(PlainLd{p_post, HH}, StoreEp{p_lin}, lW, lB, NN, HH);

        k_bn_stats<<<256, HH>>>(p_lin);
        k_bn_fin<<<1, HH>>>();
        k_apply<<<GB_NH, TPB>>>(bG, bB);

        // upd = relu([x[src], x[dst], ea] @ emlp_w1 + b1)
        gemm_mma<<<NB_E, 256>>>(GatherLd{p_x, src, dst, p_ea},
                                ReluEp{p_upd}, m1W, m1B, EE, 3 * HH);
        // ea = ea + (upd @ emlp_w2 + b2) / 2
        gemm_mma<<<NB_E, 256>>>(PlainLd{p_upd, HH}, EaEp{p_ea}, m2W, m2B, EE, HH);
    }

    k_copy_x<<<GB_NH, TPB>>>(out);
}

// round 7
// speedup vs baseline: 5.7022x; 1.0367x over previous
#include <cuda_runtime.h>
#include <cstdint>
#include <math.h>

#define NN 50000
#define EE 400000
#define EPP 40000
#define FF 64
#define EDD 32
#define HH 128
#define LL 2

// ---------------- scratch (device globals; no allocation allowed) ----------------
__device__ float g_x[NN * HH];
__device__ float g_ea[EE * HH];
__device__ float g_eenc[EE * HH];
__device__ float g_upd[EE * HH];
__device__ float g_post[NN * HH];
__device__ float g_lin[NN * HH];
__device__ float g_s1[NN * HH];   // becomes mean after finalize
__device__ float g_s2[NN * HH];   // becomes std after finalize
__device__ float g_mn[NN * HH];
__device__ float g_mx[NN * HH];
__device__ float g_wt[1664 * 128];   // tf32-rounded weight copy [K][128]
__device__ int   g_deg[NN];
__device__ float g_amp[NN];
__device__ float g_att[NN];
__device__ float g_bnsum[HH];
__device__ float g_bnsq[HH];
__device__ float g_bnmu[HH];
__device__ float g_bnrstd[HH];

// ---------------- helpers ----------------
__device__ __forceinline__ uint32_t smem_u32(const void* p) {
    uint32_t a;
    asm("{ .reg .u64 t; cvta.to.shared.u64 t, %1; cvt.u32.u64 %0, t; }" : "=r"(a) : "l"(p));
    return a;
}
__device__ __forceinline__ uint32_t f2tf32(float x) {
    uint32_t r; asm("cvt.rn.tf32.f32 %0, %1;" : "=r"(r) : "f"(x)); return r;
}
__device__ __forceinline__ void cp16(uint32_t sdst, const void* gsrc, bool full) {
    int sz = full ? 16 : 0;
    asm volatile("cp.async.cg.shared.global [%0], [%1], 16, %2;"
                 :: "r"(sdst), "l"(gsrc), "r"(sz) : "memory");
}
__device__ __forceinline__ void cp_commit() {
    asm volatile("cp.async.commit_group;" ::: "memory");
}
__device__ __forceinline__ void mma_tf32(float c[4], const uint32_t a[4], const uint32_t b[2]) {
    asm volatile(
        "mma.sync.aligned.m16n8k8.row.col.f32.tf32.tf32.f32 "
        "{%0,%1,%2,%3}, {%4,%5,%6,%7}, {%8,%9}, {%0,%1,%2,%3};\n"
        : "+f"(c[0]), "+f"(c[1]), "+f"(c[2]), "+f"(c[3])
        : "r"(a[0]), "r"(a[1]), "r"(a[2]), "r"(a[3]), "r"(b[0]), "r"(b[1]));
}

// ---------------- atomic float min/max ----------------
__device__ __forceinline__ void atomicMaxF(float* a, float v) {
    if (v >= 0.f) atomicMax((int*)a, __float_as_int(v));
    else          atomicMin((unsigned int*)a, __float_as_uint(v));
}
__device__ __forceinline__ void atomicMinF(float* a, float v) {
    if (v >= 0.f) atomicMin((int*)a, __float_as_int(v));
    else          atomicMax((unsigned int*)a, __float_as_uint(v));
}

// ---------------- A-tile loaders: ptr4(r,k) -> gmem pointer to 4 floats ----------------
struct PlainLd {
    const float* __restrict__ A; int K;
    static constexpr bool scaled = false;
    __device__ __forceinline__ const float* ptr4(int r, int k) const {
        return A + (long)r * K + k;
    }
    __device__ __forceinline__ float rowscale(int, int) const { return 1.f; }
};
struct GatherLd {  // [x[i0[r]], x[i1[r]], third[r]]  (each 128 wide)
    const float* __restrict__ x;
    const int* __restrict__ i0;
    const int* __restrict__ i1;
    const float* __restrict__ third;
    static constexpr bool scaled = false;
    __device__ __forceinline__ const float* ptr4(int r, int k) const {
        if (k < 128) return x + (long)i0[r] * 128 + k;
        if (k < 256) return x + (long)i1[r] * 128 + (k - 128);
        return third + (long)r * 128 + (k - 256);
    }
    __device__ __forceinline__ float rowscale(int, int) const { return 1.f; }
};
struct PostLd {  // [x, agg, agg*amp, agg*att]; agg = [mean, mn, mx, std]
    const float* __restrict__ x;
    const float* __restrict__ mean;
    const float* __restrict__ mn;
    const float* __restrict__ mx;
    const float* __restrict__ sd;
    const float* __restrict__ amp;
    const float* __restrict__ att;
    static constexpr bool scaled = true;
    __device__ __forceinline__ const float* ptr4(int r, int k) const {
        if (k < 128) return x + (long)r * 128 + k;
        int rem = (k - 128) & 511;
        int a   = rem >> 7;       // 0 mean, 1 mn, 2 mx, 3 std
        int c   = rem & 127;
        const float* base = (a == 0) ? mean : (a == 1) ? mn : (a == 2) ? mx : sd;
        return base + (long)r * 128 + c;
    }
    __device__ __forceinline__ float rowscale(int r, int k) const {
        if (k < 128) return 1.f;
        int grp = (k - 128) >> 9;   // 0: raw, 1: *amp, 2: *att
        return (grp == 1) ? amp[r] : (grp == 2) ? att[r] : 1.f;
    }
};

// ---------------- epilogues ----------------
struct StoreEp {
    float* __restrict__ o;
    __device__ __forceinline__ void pair(int r, int c, float v0, float v1) const {
        *(float2*)(o + (long)r * 128 + c) = make_float2(v0, v1);
    }
};
struct ReluEp {
    float* __restrict__ o;
    __device__ __forceinline__ void pair(int r, int c, float v0, float v1) const {
        *(float2*)(o + (long)r * 128 + c) = make_float2(fmaxf(v0, 0.f), fmaxf(v1, 0.f));
    }
};
struct EaEp {  // ea += v/2
    float* __restrict__ ea;
    __device__ __forceinline__ void pair(int r, int c, float v0, float v1) const {
        float2* p = (float2*)(ea + (long)r * 128 + c);
        float2 cur = *p;
        cur.x += 0.5f * v0; cur.y += 0.5f * v1;
        *p = cur;
    }
};
struct AggEp {  // segment sum / sumsq / min / max over dst
    float* __restrict__ s1; float* __restrict__ s2;
    float* __restrict__ mn; float* __restrict__ mx;
    const int* __restrict__ dst;
    __device__ __forceinline__ void one(long o, float v) const {
        atomicAdd(s1 + o, v);
        atomicAdd(s2 + o, v * v);
        atomicMaxF(mx + o, v);
        atomicMinF(mn + o, v);
    }
    __device__ __forceinline__ void pair(int r, int c, float v0, float v1) const {
        long o = (long)dst[r] * 128 + c;
        one(o, v0);
        one(o + 1, v1);
    }
};

// ---------------- weight pre-round: Wt[i] = tf32_rn(W[i]) (bit-exact with in-loop cvt) --------
__global__ void k_round_w(const float* __restrict__ W, float* __restrict__ Wt, int n) {
    int i = blockIdx.x * blockDim.x + threadIdx.x;
    if (i < n) Wt[i] = __uint_as_float(f2tf32(W[i]));
}

// ---------------- tensor-core GEMM: out[M,128] = A[M,K] @ W[K,128] + b ----------------
// 128x128 CTA tile, 256 threads = 8 warps (4 M x 2 N), warp tile 32x64.
// mma.sync m16n8k8 tf32. K chunk = 16, cp.async 3-stage pipeline.
// W must be pre-rounded to tf32 (k_round_w) -> B fragments read without cvt.
#define KT 16
#define NSTG 3
#define AP 20    // A row pitch (floats)
#define WP 136   // W row pitch (floats)

template <typename Loader, typename Epi>
__global__ void __launch_bounds__(256, 2) gemm_mma(
    Loader ld, Epi ep,
    const float* __restrict__ W, const float* __restrict__ bias,
    int M, int K)
{
    __shared__ float As[NSTG][128 * AP];
    __shared__ float Ws[NSTG][KT * WP];
    const int tid  = threadIdx.x;
    const int lane = tid & 31;
    const int wid  = tid >> 5;
    const int wm   = wid & 3;        // warp row: 32 rows each
    const int wn   = wid >> 2;       // warp col: 64 cols each
    const int gid  = lane >> 2;      // 0..7
    const int tid4 = lane & 3;       // 0..3
    const int row0 = blockIdx.x * 128;

    const int sr0 = tid >> 2,  sq0 = tid & 3;
    const int sr1 = sr0 + 64;
    const int wk0 = tid >> 5,  wc0 = tid & 31;
    const int wk1 = wk0 + 8;

    const uint32_t sA = smem_u32(&As[0][0]);
    const uint32_t sW = smem_u32(&Ws[0][0]);

    float acc[2][8][4];
#pragma unroll
    for (int mt = 0; mt < 2; mt++)
#pragma unroll
        for (int nt = 0; nt < 8; nt++)
#pragma unroll
            for (int i = 0; i < 4; i++) acc[mt][nt][i] = 0.f;

    const int nch = K / KT;

    auto stage = [&](int buf, int k0) {
        uint32_t a_base = sA + buf * (128 * AP * 4);
        uint32_t w_base = sW + buf * (KT * WP * 4);
        int g0 = row0 + sr0, g1 = row0 + sr1;
        bool v0 = g0 < M, v1 = g1 < M;
        cp16(a_base + (sr0 * AP + sq0 * 4) * 4, ld.ptr4(v0 ? g0 : 0, k0 + sq0 * 4), v0);
        cp16(a_base + (sr1 * AP + sq0 * 4) * 4, ld.ptr4(v1 ? g1 : 0, k0 + sq0 * 4), v1);
        cp16(w_base + (wk0 * WP + wc0 * 4) * 4, W + (long)(k0 + wk0) * 128 + wc0 * 4, true);
        cp16(w_base + (wk1 * WP + wc0 * 4) * 4, W + (long)(k0 + wk1) * 128 + wc0 * 4, true);
        cp_commit();
    };

    stage(0, 0);
    if (nch > 1) stage(1, KT);

    for (int ch = 0; ch < nch; ch++) {
        const int buf = ch % NSTG;
        const int k0 = ch * KT;
        if (ch + 2 < nch) {
            stage((ch + 2) % NSTG, k0 + 2 * KT);
            asm volatile("cp.async.wait_group 2;" ::: "memory");
        } else if (ch + 1 < nch) {
            asm volatile("cp.async.wait_group 1;" ::: "memory");
        } else {
            asm volatile("cp.async.wait_group 0;" ::: "memory");
        }
        __syncthreads();

        // per-chunk row scales (PostLd only)
        float rs[2][2];
        if constexpr (Loader::scaled) {
#pragma unroll
            for (int mt = 0; mt < 2; mt++) {
                int m0 = row0 + wm * 32 + mt * 16;
                int rA = m0 + gid, rB = m0 + 8 + gid;
                rs[mt][0] = ld.rowscale(rA < M ? rA : 0, k0);
                rs[mt][1] = ld.rowscale(rB < M ? rB : 0, k0);
            }
        }

        const float* Ab = &As[buf][0];
        const float* Wb = &Ws[buf][0];
#pragma unroll
        for (int ks = 0; ks < KT; ks += 8) {
            uint32_t a[2][4];
#pragma unroll
            for (int mt = 0; mt < 2; mt++) {
                int m0 = wm * 32 + mt * 16;
                float a0 = Ab[(m0 + gid) * AP + ks + tid4];
                float a1 = Ab[(m0 + 8 + gid) * AP + ks + tid4];
                float a2 = Ab[(m0 + gid) * AP + ks + tid4 + 4];
                float a3 = Ab[(m0 + 8 + gid) * AP + ks + tid4 + 4];
                if constexpr (Loader::scaled) {
                    a0 *= rs[mt][0]; a1 *= rs[mt][1];
                    a2 *= rs[mt][0]; a3 *= rs[mt][1];
                }
                a[mt][0] = f2tf32(a0); a[mt][1] = f2tf32(a1);
                a[mt][2] = f2tf32(a2); a[mt][3] = f2tf32(a3);
            }
            uint32_t b[8][2];
#pragma unroll
            for (int nt = 0; nt < 8; nt++) {
                int n = wn * 64 + nt * 8 + gid;
                b[nt][0] = __float_as_uint(Wb[(ks + tid4) * WP + n]);       // pre-rounded
                b[nt][1] = __float_as_uint(Wb[(ks + tid4 + 4) * WP + n]);
            }
#pragma unroll
            for (int mt = 0; mt < 2; mt++)
#pragma unroll
                for (int nt = 0; nt < 8; nt++)
                    mma_tf32(acc[mt][nt], a[mt], b[nt]);
        }
        __syncthreads();
    }

    // epilogue
    float bv[8][2];
#pragma unroll
    for (int nt = 0; nt < 8; nt++) {
        int c = wn * 64 + nt * 8 + 2 * tid4;
        bv[nt][0] = bias[c];
        bv[nt][1] = bias[c + 1];
    }
#pragma unroll
    for (int mt = 0; mt < 2; mt++) {
        int rA = row0 + wm * 32 + mt * 16 + gid;
        int rB = rA + 8;
#pragma unroll
        for (int nt = 0; nt < 8; nt++) {
            int c = wn * 64 + nt * 8 + 2 * tid4;
            if (rA < M) ep.pair(rA, c, acc[mt][nt][0] + bv[nt][0], acc[mt][nt][1] + bv[nt][1]);
            if (rB < M) ep.pair(rB, c, acc[mt][nt][2] + bv[nt][0], acc[mt][nt][3] + bv[nt][1]);
        }
    }
}

// ---------------- small kernels ----------------
__global__ void k_zero_deg() {
    int i = blockIdx.x * blockDim.x + threadIdx.x;
    if (i < NN) g_deg[i] = 0;
}
__global__ void k_count_deg(const int* __restrict__ dst) {
    int e = blockIdx.x * blockDim.x + threadIdx.x;
    if (e < EE) atomicAdd(&g_deg[dst[e]], 1);
}
__global__ void k_amp_att(const float* __restrict__ adl) {
    int i = blockIdx.x * blockDim.x + threadIdx.x;
    if (i < NN) {
        float d = fmaxf((float)g_deg[i], 1.f);
        float lg = logf(d + 1.f);
        float a = adl[0];
        g_amp[i] = lg / a;
        g_att[i] = a / lg;
    }
}
__global__ void k_init_agg() {
    long i = (long)blockIdx.x * blockDim.x + threadIdx.x;
    if (i < (long)NN * HH) {
        g_s1[i] = 0.f;
        g_s2[i] = 0.f;
        g_mn[i] = __int_as_float(0x7f800000);   // +inf
        g_mx[i] = __int_as_float(0xff800000);   // -inf
    }
}
__global__ void k_zero_bn() {
    int c = threadIdx.x;
    g_bnsum[c] = 0.f;
    g_bnsq[c] = 0.f;
}
__global__ void k_fin_agg() {
    long i = (long)blockIdx.x * blockDim.x + threadIdx.x;
    if (i < (long)NN * HH) {
        int n = (int)(i >> 7);
        int d = g_deg[n];
        float degc = fmaxf((float)d, 1.f);
        float m = g_s1[i] / degc;
        float var = g_s2[i] / degc - m * m;
        g_s1[i] = m;
        g_s2[i] = sqrtf(fmaxf(var, 0.f) + 1e-5f);
        if (d == 0) { g_mn[i] = 0.f; g_mx[i] = 0.f; }
    }
}
__global__ void k_bn_stats(const float* __restrict__ o) {
    int c = threadIdx.x;           // 128 threads
    float s = 0.f, s2 = 0.f;
    for (int r = blockIdx.x; r < NN; r += gridDim.x) {
        float v = o[(long)r * 128 + c];
        s += v; s2 += v * v;
    }
    atomicAdd(&g_bnsum[c], s);
    atomicAdd(&g_bnsq[c], s2);
}
__global__ void k_bn_fin() {
    int c = threadIdx.x;
    float mu = g_bnsum[c] / (float)NN;
    float var = g_bnsq[c] / (float)NN - mu * mu;
    g_bnmu[c] = mu;
    g_bnrstd[c] = rsqrtf(var + 1e-5f);
}
__global__ void k_apply(const float* __restrict__ bng, const float* __restrict__ bnb) {
    long i = (long)blockIdx.x * blockDim.x + threadIdx.x;
    if (i < (long)NN * HH) {
        int c = (int)(i & 127);
        float v = bng[c] * (g_lin[i] - g_bnmu[c]) * g_bnrstd[c] + bnb[c];
        g_x[i] = (g_x[i] + fmaxf(v, 0.f)) * 0.5f;
    }
}
__global__ void k_copy_x(float* __restrict__ o) {
    long i = (long)blockIdx.x * blockDim.x + threadIdx.x;
    if (i < (long)NN * HH) o[i] = g_x[i];
}

// ---------------- launch ----------------
extern "C" void kernel_launch(void* const* d_in, const int* in_sizes, int n_in,
                              void* d_out, int out_size) {
    const float* x_in       = (const float*)d_in[0];
    const int*   eidx       = (const int*)  d_in[1];
    const float* edge_attr  = (const float*)d_in[2];
    const float* pos_attr   = (const float*)d_in[4];
    const float* neg_attr   = (const float*)d_in[6];
    const float* avg_dl     = (const float*)d_in[7];
    const float* node_emb_w = (const float*)d_in[8];
    const float* node_emb_b = (const float*)d_in[9];
    const float* edge_emb_w = (const float*)d_in[10];
    const float* edge_emb_b = (const float*)d_in[11];
    const float* eenc_w     = (const float*)d_in[12];
    const float* eenc_b     = (const float*)d_in[13];
    const float* pre_w      = (const float*)d_in[14];
    const float* pre_b      = (const float*)d_in[15];
    const float* post_w     = (const float*)d_in[16];
    const float* post_b     = (const float*)d_in[17];
    const float* lin_w      = (const float*)d_in[18];
    const float* lin_b      = (const float*)d_in[19];
    const float* emlp_w1    = (const float*)d_in[20];
    const float* emlp_b1    = (const float*)d_in[21];
    const float* emlp_w2    = (const float*)d_in[22];
    const float* emlp_b2    = (const float*)d_in[23];
    const float* bn_g       = (const float*)d_in[24];
    const float* bn_b       = (const float*)d_in[25];

    const int* src = eidx;          // edge_index[0]
    const int* dst = eidx + EE;     // edge_index[1]

    float* out     = (float*)d_out;
    float* pos_out = out + (long)NN * HH;
    float* neg_out = pos_out + (long)EPP * HH;

    float *p_x, *p_ea, *p_eenc, *p_upd, *p_post, *p_lin, *p_s1, *p_s2, *p_mn, *p_mx, *p_amp, *p_att, *p_wt;
    cudaGetSymbolAddress((void**)&p_x, g_x);
    cudaGetSymbolAddress((void**)&p_ea, g_ea);
    cudaGetSymbolAddress((void**)&p_eenc, g_eenc);
    cudaGetSymbolAddress((void**)&p_upd, g_upd);
    cudaGetSymbolAddress((void**)&p_post, g_post);
    cudaGetSymbolAddress((void**)&p_lin, g_lin);
    cudaGetSymbolAddress((void**)&p_s1, g_s1);
    cudaGetSymbolAddress((void**)&p_s2, g_s2);
    cudaGetSymbolAddress((void**)&p_mn, g_mn);
    cudaGetSymbolAddress((void**)&p_mx, g_mx);
    cudaGetSymbolAddress((void**)&p_amp, g_amp);
    cudaGetSymbolAddress((void**)&p_att, g_att);
    cudaGetSymbolAddress((void**)&p_wt, g_wt);

    const int NB_N  = (NN + 127) / 128;      // 391
    const int NB_E  = (EE + 127) / 128;      // 3125
    const int NB_EP = (EPP + 127) / 128;     // 313
    const int TPB = 256;
    const int GB_N = (NN + TPB - 1) / TPB;
    const int GB_E = (EE + TPB - 1) / TPB;
    const long NH = (long)NN * HH;
    const int GB_NH = (int)((NH + TPB - 1) / TPB);

    auto roundW = [&](const float* w, int K) {
        k_round_w<<<(K * 128 + 255) / 256, 256>>>(w, p_wt, K * 128);
    };

    // degree + amp/att (static over layers)
    k_zero_deg<<<GB_N, TPB>>>();
    k_count_deg<<<GB_E, TPB>>>(dst);
    k_amp_att<<<GB_N, TPB>>>(avg_dl);

    // embeddings
    roundW(node_emb_w, FF);
    gemm_mma<<<NB_N, 256>>>(PlainLd{x_in, FF}, StoreEp{p_x}, p_wt, node_emb_b, NN, FF);
    roundW(edge_emb_w, EDD);
    gemm_mma<<<NB_E, 256>>>(PlainLd{edge_attr, EDD}, StoreEp{p_ea}, p_wt, edge_emb_b, EE, EDD);
    gemm_mma<<<NB_EP, 256>>>(PlainLd{pos_attr, EDD}, StoreEp{pos_out}, p_wt, edge_emb_b, EPP, EDD);
    gemm_mma<<<NB_EP, 256>>>(PlainLd{neg_attr, EDD}, StoreEp{neg_out}, p_wt, edge_emb_b, EPP, EDD);

    for (int l = 0; l < LL; l++) {
        const float* eW  = eenc_w  + (long)l * HH * HH;
        const float* eB  = eenc_b  + (long)l * HH;
        const float* pW  = pre_w   + (long)l * 3 * HH * HH;
        const float* pB  = pre_b   + (long)l * HH;
        const float* poW = post_w  + (long)l * 13 * HH * HH;
        const float* poB = post_b  + (long)l * HH;
        const float* lW  = lin_w   + (long)l * HH * HH;
        const float* lB  = lin_b   + (long)l * HH;
        const float* m1W = emlp_w1 + (long)l * 3 * HH * HH;
        const float* m1B = emlp_b1 + (long)l * HH;
        const float* m2W = emlp_w2 + (long)l * HH * HH;
        const float* m2B = emlp_b2 + (long)l * HH;
        const float* bG  = bn_g    + (long)l * HH;
        const float* bB  = bn_b    + (long)l * HH;

        k_init_agg<<<GB_NH, TPB>>>();
        k_zero_bn<<<1, HH>>>();

        // e_enc = ea @ eenc_w + b
        roundW(eW, HH);
        gemm_mma<<<NB_E, 256>>>(PlainLd{p_ea, HH}, StoreEp{p_eenc}, p_wt, eB, EE, HH);

        // h = [x[dst], x[src], e_enc] @ pre_w + b   (fused segment agg epilogue)
        roundW(pW, 3 * HH);
        gemm_mma<<<NB_E, 256>>>(GatherLd{p_x, dst, src, p_eenc},
                                AggEp{p_s1, p_s2, p_mn, p_mx, dst}, p_wt, pB, EE, 3 * HH);

        k_fin_agg<<<GB_NH, TPB>>>();

        // out = [x, agg, agg*amp, agg*att] @ post_w + b
        roundW(poW, 13 * HH);
        gemm_mma<<<NB_N, 256>>>(PostLd{p_x, p_s1, p_mn, p_mx, p_s2, p_amp, p_att},
                                StoreEp{p_post}, p_wt, poB, NN, 13 * HH);
        // out = out @ lin_w + b
        roundW(lW, HH);
        gemm_mma<<<NB_N, 256>>>(PlainLd{p_post, HH}, StoreEp{p_lin}, p_wt, lB, NN, HH);

        k_bn_stats<<<256, HH>>>(p_lin);
        k_bn_fin<<<1, HH>>>();
        k_apply<<<GB_NH, TPB>>>(bG, bB);

        // upd = relu([x[src], x[dst], ea] @ emlp_w1 + b1)
        roundW(m1W, 3 * HH);
        gemm_mma<<<NB_E, 256>>>(GatherLd{p_x, src, dst, p_ea},
                                ReluEp{p_upd}, p_wt, m1B, EE, 3 * HH);
        // ea = ea + (upd @ emlp_w2 + b2) / 2
        roundW(m2W, HH);
        gemm_mma<<<NB_E, 256>>>(PlainLd{p_upd, HH}, EaEp{p_ea}, p_wt, m2B, EE, HH);
    }

    k_copy_x<<<GB_NH, TPB>>>(out);
}